// round 2
// baseline (speedup 1.0000x reference)
#include <cuda_runtime.h>
#include <cuda_bf16.h>

// Problem constants
#define BB 4
#define SS 1024
#define KK 1024
#define DD 1024
#define HH 16
#define HD 64
#define MRD 4096          // MR * D
#define SIXD 6144
#define NBS 4096          // B * S  (== B * K)
#define INV_SQRT_HD 0.125f
#define GELU_C 0.7978845608028654f

// ---------------- scratch (static device globals; no allocation) ----------------
__device__ float g_mod[BB * SIXD];
__device__ float g_qn[NBS * DD];
__device__ float g_kvn[NBS * DD];
__device__ float g_q[NBS * DD];
__device__ float g_kv[NBS * 2 * DD];
__device__ float g_scores[(size_t)BB * HH * SS * KK];   // 64M floats = 256MB
__device__ float g_attn[NBS * DD];
__device__ float g_x[NBS * DD];
__device__ float g_h[NBS * DD];
__device__ float g_h1[(size_t)NBS * MRD];               // 64MB
__device__ float g_h2[NBS * DD];
__device__ int   g_enIsByte;

// ---------------- reductions ----------------
__device__ __forceinline__ float warpSum(float v) {
    #pragma unroll
    for (int o = 16; o; o >>= 1) v += __shfl_xor_sync(0xffffffffu, v, o);
    return v;
}
__device__ __forceinline__ float warpMax(float v) {
    #pragma unroll
    for (int o = 16; o; o >>= 1) v = fmaxf(v, __shfl_xor_sync(0xffffffffu, v, o));
    return v;
}
// 256-thread block reduce (8 warps). sh must have >= 8 floats.
__device__ __forceinline__ float blockSum(float v, float* sh) {
    int tid = threadIdx.x;
    v = warpSum(v);
    if ((tid & 31) == 0) sh[tid >> 5] = v;
    __syncthreads();
    if (tid == 0) {
        float t = 0.f;
        #pragma unroll
        for (int i = 0; i < 8; i++) t += sh[i];
        sh[0] = t;
    }
    __syncthreads();
    float r = sh[0];
    __syncthreads();
    return r;
}
__device__ __forceinline__ float blockMax(float v, float* sh) {
    int tid = threadIdx.x;
    v = warpMax(v);
    if ((tid & 31) == 0) sh[tid >> 5] = v;
    __syncthreads();
    if (tid == 0) {
        float t = -3.0e38f;
        #pragma unroll
        for (int i = 0; i < 8; i++) t = fmaxf(t, sh[i]);
        sh[0] = t;
    }
    __syncthreads();
    float r = sh[0];
    __syncthreads();
    return r;
}

// ---------------- detect query_enabled dtype (int32 vs byte-packed bool) ----------------
// Reads only the first 4096 bytes (valid under either layout). If any int32 word
// has bits outside {0,1}, the buffer must be byte-packed bools.
__global__ void __launch_bounds__(1024) detect_en_k(const int* __restrict__ en32) {
    __shared__ int sh[32];
    int v = en32[threadIdx.x];
    int f = (v & ~1) ? 1 : 0;
    #pragma unroll
    for (int o = 16; o; o >>= 1) f |= __shfl_xor_sync(0xffffffffu, f, o);
    if ((threadIdx.x & 31) == 0) sh[threadIdx.x >> 5] = f;
    __syncthreads();
    if (threadIdx.x == 0) {
        int t = 0;
        #pragma unroll
        for (int i = 0; i < 32; i++) t |= sh[i];
        g_enIsByte = t;
    }
}

// ---------------- adaLN modulation: mod[b, :] = t_cond[b] @ adaW + adab ----------------
__global__ void __launch_bounds__(256) mod_k(const float* __restrict__ t_cond,
                                             const float* __restrict__ adaW,
                                             const float* __restrict__ adab,
                                             float* __restrict__ mod) {
    __shared__ float tc[1024];
    int b  = blockIdx.x / 24;
    int cg = blockIdx.x % 24;
    for (int i = threadIdx.x; i < 1024; i += 256) tc[i] = t_cond[b * 1024 + i];
    __syncthreads();
    int col = cg * 256 + threadIdx.x;
    float acc = adab[col];
    #pragma unroll 4
    for (int i = 0; i < 1024; i++) acc = fmaf(tc[i], adaW[(size_t)i * SIXD + col], acc);
    mod[b * SIXD + col] = acc;
}

// ---------------- LayerNorm (+ optional adaLN shift/scale) ----------------
__global__ void __launch_bounds__(256) ln_mod_k(const float* __restrict__ x,
                                                const float* __restrict__ w,
                                                const float* __restrict__ mod,
                                                int shOff, int scOff, int useMod,
                                                float* __restrict__ out) {
    __shared__ float sh[8];
    int row = blockIdx.x;          // 0..NBS-1
    int b = row >> 10;
    const float* xr = x + (size_t)row * DD;
    int tid = threadIdx.x;
    float v[4];
    float s = 0.f, s2 = 0.f;
    #pragma unroll
    for (int j = 0; j < 4; j++) {
        v[j] = xr[tid + j * 256];
        s += v[j];
        s2 = fmaf(v[j], v[j], s2);
    }
    s  = blockSum(s, sh);
    s2 = blockSum(s2, sh);
    float mu = s * (1.0f / DD);
    float var = s2 * (1.0f / DD) - mu * mu;
    float rs = rsqrtf(var + 1e-5f);
    float* orow = out + (size_t)row * DD;
    #pragma unroll
    for (int j = 0; j < 4; j++) {
        int d = tid + j * 256;
        float y = (v[j] - mu) * rs * w[d];
        if (useMod) {
            y = y * (1.0f + mod[b * SIXD + scOff + d]) + mod[b * SIXD + shOff + d];
        }
        orow[d] = y;
    }
}

// ---------------- generic strided-batched GEMM: C = A @ B (or A @ B^T) ----------------
template <bool TB>
__global__ void __launch_bounds__(256) gemm_k(const float* __restrict__ A,
                                              const float* __restrict__ B,
                                              float* __restrict__ C,
                                              int M, int N, int Kd,
                                              int lda, int ldb, int ldc,
                                              long long sAo, long long sAi,
                                              long long sBo, long long sBi,
                                              long long sCo, long long sCi,
                                              int nInner) {
    int zo = blockIdx.z / nInner, zi = blockIdx.z % nInner;
    A += (size_t)zo * sAo + (size_t)zi * sAi;
    B += (size_t)zo * sBo + (size_t)zi * sBi;
    C += (size_t)zo * sCo + (size_t)zi * sCi;

    __shared__ float As[16][128];
    __shared__ float Bs[16][128];

    const int tid = threadIdx.x;
    const int tx = tid & 15, ty = tid >> 4;
    const int row0 = blockIdx.y * 128, col0 = blockIdx.x * 128;
    const int arow = tid >> 2;
    const int akk  = (tid & 3) << 2;

    float acc[8][8];
    #pragma unroll
    for (int i = 0; i < 8; i++)
        #pragma unroll
        for (int j = 0; j < 8; j++) acc[i][j] = 0.f;

    for (int k0 = 0; k0 < Kd; k0 += 16) {
        #pragma unroll
        for (int p = 0; p < 2; p++) {
            int r = arow + p * 64;
            int gr = row0 + r;
            float4 v = make_float4(0.f, 0.f, 0.f, 0.f);
            if (gr < M) v = *(const float4*)(A + (size_t)gr * lda + k0 + akk);
            As[akk + 0][r] = v.x; As[akk + 1][r] = v.y;
            As[akk + 2][r] = v.z; As[akk + 3][r] = v.w;
        }
        if (!TB) {
            #pragma unroll
            for (int p = 0; p < 2; p++) {
                int kr = (tid >> 5) + p * 8;
                int cc = (tid & 31) << 2;
                int gc = col0 + cc;
                float4 v = make_float4(0.f, 0.f, 0.f, 0.f);
                if (gc + 4 <= N) v = *(const float4*)(B + (size_t)(k0 + kr) * ldb + gc);
                *(float4*)&Bs[kr][cc] = v;
            }
        } else {
            #pragma unroll
            for (int p = 0; p < 2; p++) {
                int n = (tid >> 2) + p * 64;
                int gc = col0 + n;
                float4 v = make_float4(0.f, 0.f, 0.f, 0.f);
                if (gc < N) v = *(const float4*)(B + (size_t)gc * ldb + k0 + akk);
                Bs[akk + 0][n] = v.x; Bs[akk + 1][n] = v.y;
                Bs[akk + 2][n] = v.z; Bs[akk + 3][n] = v.w;
            }
        }
        __syncthreads();
        #pragma unroll
        for (int kk = 0; kk < 16; kk++) {
            float a[8], b[8];
            *(float4*)&a[0] = *(const float4*)&As[kk][ty * 8];
            *(float4*)&a[4] = *(const float4*)&As[kk][ty * 8 + 4];
            *(float4*)&b[0] = *(const float4*)&Bs[kk][tx * 8];
            *(float4*)&b[4] = *(const float4*)&Bs[kk][tx * 8 + 4];
            #pragma unroll
            for (int i = 0; i < 8; i++)
                #pragma unroll
                for (int j = 0; j < 8; j++)
                    acc[i][j] = fmaf(a[i], b[j], acc[i][j]);
        }
        __syncthreads();
    }
    #pragma unroll
    for (int i = 0; i < 8; i++) {
        int gr = row0 + ty * 8 + i;
        if (gr >= M) continue;
        float* cp = C + (size_t)gr * ldc;
        #pragma unroll
        for (int j = 0; j < 8; j++) {
            int gc = col0 + tx * 8 + j;
            if (gc < N) cp[gc] = acc[i][j];
        }
    }
}

// ---------------- RoPE (in-place, half-rotation pairing d <-> d+32) ----------------
__global__ void __launch_bounds__(256) rope_k(float* __restrict__ x,
                                              const float* __restrict__ cosp,
                                              const float* __restrict__ sinp,
                                              int rowStride) {
    int idx = blockIdx.x * 256 + threadIdx.x;   // NBS*H*32 threads
    int d = idx & 31;
    int h = (idx >> 5) & 15;
    int rs = idx >> 9;                           // row over B*S
    int s = rs & 1023;
    float* p = x + (size_t)rs * rowStride + h * HD + d;
    float x1 = p[0], x2 = p[32];
    float c1 = cosp[s * HD + d],      sn1 = sinp[s * HD + d];
    float c2 = cosp[s * HD + d + 32], sn2 = sinp[s * HD + d + 32];
    p[0]  = x1 * c1 - x2 * sn1;
    p[32] = x2 * c2 + x1 * sn2;
}

// ---------------- masked softmax over scores rows (scale + group mask fused) ----------------
__global__ void __launch_bounds__(256) softmax_k(float* __restrict__ sc,
                                                 const int* __restrict__ grp) {
    __shared__ float sh[8];
    int r = blockIdx.x;             // b*H*S + h*S + q
    int q = r & 1023;
    int b = r >> 14;
    float* p = sc + (size_t)r * KK;
    int gq = grp[(b << 10) + q];
    int tid = threadIdx.x;
    float v[4];
    float mx = -3.0e38f;
    #pragma unroll
    for (int j = 0; j < 4; j++) {
        int i = tid + j * 256;
        float s = p[i];
        s = (grp[(b << 10) + i] != gq) ? s * INV_SQRT_HD : -1.0e9f;
        v[j] = s;
        mx = fmaxf(mx, s);
    }
    mx = blockMax(mx, sh);
    float sum = 0.f;
    #pragma unroll
    for (int j = 0; j < 4; j++) {
        v[j] = __expf(v[j] - mx);
        sum += v[j];
    }
    sum = blockSum(sum, sh);
    float inv = 1.0f / sum;
    #pragma unroll
    for (int j = 0; j < 4; j++) p[tid + j * 256] = v[j] * inv;
}

// ---------------- bias + gelu(tanh) in-place on h1 ----------------
__global__ void __launch_bounds__(256) biasgelu_k(float* __restrict__ h1,
                                                  const float* __restrict__ b1) {
    size_t i = (size_t)blockIdx.x * 256 + threadIdx.x;
    float v = h1[i] + b1[i & (MRD - 1)];
    float u = GELU_C * (v + 0.044715f * v * v * v);
    u = fminf(fmaxf(u, -15.f), 15.f);
    float t = __expf(2.0f * u);
    float th = (t - 1.0f) / (t + 1.0f);
    h1[i] = 0.5f * v * (1.0f + th);
}

// ---------------- gated residual: out = base + gate*(g_vec ⊙ (acc [+ bias])) ----------------
__global__ void __launch_bounds__(256) resid_k(const float* __restrict__ acc,
                                               const float* __restrict__ base,
                                               const float* __restrict__ bias,
                                               const float* __restrict__ mod,
                                               int goff,
                                               const void* __restrict__ en,
                                               float* __restrict__ out) {
    size_t i = (size_t)blockIdx.x * 256 + threadIdx.x;
    int d = (int)(i & 1023);
    size_t rs = i >> 10;
    int b = (int)(rs >> 10);
    int e = g_enIsByte ? (int)((const unsigned char*)en)[rs]
                       : ((const int*)en)[rs];
    float g = e ? mod[b * SIXD + goff + d] : 0.f;
    float a = acc[i];
    if (bias) a += bias[d];
    out[i] = base[i] + g * a;
}

// ---------------- host launcher ----------------
static void launch_gemm(bool tb, const float* A, const float* B, float* C,
                        int M, int N, int K, int lda, int ldb, int ldc,
                        long long sAo, long long sAi, long long sBo, long long sBi,
                        long long sCo, long long sCi, int nInner, int nz) {
    dim3 g((N + 127) / 128, (M + 127) / 128, nz);
    if (tb)
        gemm_k<true><<<g, 256>>>(A, B, C, M, N, K, lda, ldb, ldc,
                                 sAo, sAi, sBo, sBi, sCo, sCi, nInner);
    else
        gemm_k<false><<<g, 256>>>(A, B, C, M, N, K, lda, ldb, ldc,
                                  sAo, sAi, sBo, sBi, sCo, sCi, nInner);
}

extern "C" void kernel_launch(void* const* d_in, const int* in_sizes, int n_in,
                              void* d_out, int out_size) {
    const float* q_x    = (const float*)d_in[0];
    const float* kv_x   = (const float*)d_in[1];
    const float* t_cond = (const float*)d_in[2];
    const float* cos_q  = (const float*)d_in[3];
    const float* sin_q  = (const float*)d_in[4];
    const float* cos_k  = (const float*)d_in[5];
    const float* sin_k  = (const float*)d_in[6];
    const int*   grp    = (const int*)d_in[7];
    const void*  en     = d_in[8];
    const float* qn_w   = (const float*)d_in[9];
    const float* kvn_w  = (const float*)d_in[10];
    const float* n2_w   = (const float*)d_in[11];
    const float* Wq     = (const float*)d_in[12];
    const float* Wkv    = (const float*)d_in[13];
    const float* Wo     = (const float*)d_in[14];
    const float* W1     = (const float*)d_in[15];
    const float* b1     = (const float*)d_in[16];
    const float* W2     = (const float*)d_in[17];
    const float* b2     = (const float*)d_in[18];
    const float* adaW   = (const float*)d_in[19];
    const float* adab   = (const float*)d_in[20];
    float* out = (float*)d_out;

    float *mod, *qn, *kvn, *q, *kv, *scores, *attn, *x, *h, *h1, *h2;
    cudaGetSymbolAddress((void**)&mod,    g_mod);
    cudaGetSymbolAddress((void**)&qn,     g_qn);
    cudaGetSymbolAddress((void**)&kvn,    g_kvn);
    cudaGetSymbolAddress((void**)&q,      g_q);
    cudaGetSymbolAddress((void**)&kv,     g_kv);
    cudaGetSymbolAddress((void**)&scores, g_scores);
    cudaGetSymbolAddress((void**)&attn,   g_attn);
    cudaGetSymbolAddress((void**)&x,      g_x);
    cudaGetSymbolAddress((void**)&h,      g_h);
    cudaGetSymbolAddress((void**)&h1,     g_h1);
    cudaGetSymbolAddress((void**)&h2,     g_h2);

    // 0. detect query_enabled dtype
    detect_en_k<<<1, 1024>>>((const int*)en);

    // 1. adaLN modulation vector
    mod_k<<<BB * (SIXD / 256), 256>>>(t_cond, adaW, adab, mod);

    // 2. LN + msa modulation on q_x; plain LN on kv_x
    ln_mod_k<<<NBS, 256>>>(q_x, qn_w, mod, 0, DD, 1, qn);
    ln_mod_k<<<NBS, 256>>>(kv_x, kvn_w, mod, 0, 0, 0, kvn);

    // 3. Projections
    launch_gemm(false, qn, Wq, q, NBS, DD, DD, DD, DD, DD, 0, 0, 0, 0, 0, 0, 1, 1);
    launch_gemm(false, kvn, Wkv, kv, NBS, 2 * DD, DD, DD, 2 * DD, 2 * DD, 0, 0, 0, 0, 0, 0, 1, 1);

    // 4. RoPE on q and on k-half of kv
    rope_k<<<(NBS * HH * 32) / 256, 256>>>(q, cos_q, sin_q, DD);
    rope_k<<<(NBS * HH * 32) / 256, 256>>>(kv, cos_k, sin_k, 2 * DD);

    // 5. scores[b,h] = Q_bh (S x HD) @ K_bh^T (HD x K)
    launch_gemm(true, q, kv, scores,
                SS, KK, HD,
                DD, 2 * DD, KK,
                (long long)SS * DD, HD,
                (long long)KK * 2 * DD, HD,
                (long long)HH * SS * KK, (long long)SS * KK,
                HH, BB * HH);

    // 6. scale + group mask + softmax
    softmax_k<<<BB * HH * SS, 256>>>(scores, grp);

    // 7. attn[b,h] = P (S x K) @ V_bh (K x HD)
    launch_gemm(false, scores, kv + DD, attn,
                SS, HD, KK,
                KK, 2 * DD, DD,
                (long long)HH * SS * KK, (long long)SS * KK,
                (long long)KK * 2 * DD, HD,
                (long long)SS * DD, HD,
                HH, BB * HH);

    // 8. attn @ Wo, then gated residual -> x
    launch_gemm(false, attn, Wo, h2, NBS, DD, DD, DD, DD, DD, 0, 0, 0, 0, 0, 0, 1, 1);
    resid_k<<<(NBS * DD) / 256, 256>>>(h2, q_x, nullptr, mod, 2 * DD, en, x);

    // 9. LN + mlp modulation
    ln_mod_k<<<NBS, 256>>>(x, n2_w, mod, 3 * DD, 4 * DD, 1, h);

    // 10. MLP
    launch_gemm(false, h, W1, h1, NBS, MRD, DD, DD, MRD, MRD, 0, 0, 0, 0, 0, 0, 1, 1);
    biasgelu_k<<<(int)(((size_t)NBS * MRD) / 256), 256>>>(h1, b1);
    launch_gemm(false, h1, W2, h2, NBS, DD, MRD, MRD, DD, DD, 0, 0, 0, 0, 0, 0, 1, 1);

    // 11. final gated residual -> out
    resid_k<<<(NBS * DD) / 256, 256>>>(h2, x, b2, mod, 5 * DD, en, out);
}

// round 5
// speedup vs baseline: 2.9836x; 2.9836x over previous
#include <cuda_runtime.h>
#include <cstdint>

// Problem constants
#define BB 4
#define SS 1024
#define KK 1024
#define DD 1024
#define HH 16
#define HD 64
#define MRD 4096          // MR * D
#define SIXD 6144
#define NBS 4096          // B * S  (== B * K)
#define INV_SQRT_HD 0.125f
#define GELU_C 0.7978845608028654f

// ---------------- scratch (static device globals; no allocation) ----------------
__device__ float g_mod[BB * SIXD];
__device__ float g_qn[NBS * DD];
__device__ float g_kvn[NBS * DD];
__device__ float g_q[NBS * DD];
__device__ float g_kv[NBS * 2 * DD];
__device__ float g_scores[(size_t)BB * HH * SS * KK];   // 256MB
__device__ float g_attn[NBS * DD];
__device__ float g_x[NBS * DD];
__device__ float g_h[NBS * DD];
__device__ float g_h1[(size_t)NBS * MRD];               // 64MB
__device__ float g_h2[NBS * DD];
__device__ int   g_enIsByte;

// ================= PTX helpers (sm_80-safe only) =================
__device__ __forceinline__ uint32_t smem_u32(const void* p) {
    uint32_t a;
    asm("{ .reg .u64 t; cvta.to.shared.u64 t, %1; cvt.u32.u64 %0, t; }" : "=r"(a) : "l"(p));
    return a;
}
#define CP_ASYNC16(sa, ga) \
    asm volatile("cp.async.ca.shared.global [%0], [%1], 16;" :: "r"(sa), "l"(ga) : "memory")
#define CP_COMMIT() asm volatile("cp.async.commit_group;" ::: "memory")
#define CP_WAIT0()  asm volatile("cp.async.wait_group 0;" ::: "memory")
#define CP_WAIT1()  asm volatile("cp.async.wait_group 1;" ::: "memory")

__device__ __forceinline__ void mma_tf32_16x8x8(float* c, const uint32_t* a, const uint32_t* b) {
    asm volatile(
        "mma.sync.aligned.m16n8k8.row.col.f32.tf32.tf32.f32 "
        "{%0,%1,%2,%3}, {%4,%5,%6,%7}, {%8,%9}, {%0,%1,%2,%3};"
        : "+f"(c[0]), "+f"(c[1]), "+f"(c[2]), "+f"(c[3])
        : "r"(a[0]), "r"(a[1]), "r"(a[2]), "r"(a[3]), "r"(b[0]), "r"(b[1]));
}

// ================= mma.sync tf32 GEMM =================
// C[M,N] = A[M,K] @ B. Row-major fp32.
// B in GMEM: [N,K] if TRB (e.g. K-matrix [token, hd]); else [K,N] (weights / V).
// CTA tile 128 x NT, BK=32, 8 warps (2 rows x 4 cols), 2-stage cp.async pipeline.
template <int NT, bool TRB>
__global__ void __launch_bounds__(256) gemm_mma(
    const float* __restrict__ A, const float* __restrict__ B, float* __restrict__ C,
    int Kd, int lda, int ldb, int ldc,
    long long sAo, long long sAi, long long sBo, long long sBi,
    long long sCo, long long sCi, int nInner)
{
    constexpr int APAD = 36;                  // 128 x 36 floats per A stage
    constexpr int ASZ  = 128 * APAD;
    constexpr int BPAD = TRB ? 36 : (NT + 8);
    constexpr int BROWS = TRB ? NT : 32;
    constexpr int BSZ  = BROWS * BPAD;
    constexpr int WNT  = NT / 4;              // warp col width (32 or 16)
    constexpr int NTL  = WNT / 8;             // n tiles per warp (4 or 2)

    extern __shared__ float sm[];
    uint32_t smw = smem_u32(sm);              // byte address of smem base

    const int tid = threadIdx.x;
    const int lane = tid & 31;
    const int wid = tid >> 5;
    const int wm = wid >> 2;                  // 0..1  (64 rows each)
    const int wn = wid & 3;                   // 0..3
    const int lq = lane >> 2;                 // 0..7
    const int lr = lane & 3;                  // 0..3

    const int zo = blockIdx.z / nInner, zi = blockIdx.z % nInner;
    A += (size_t)zo * sAo + (size_t)zi * sAi;
    B += (size_t)zo * sBo + (size_t)zi * sBi;
    C += (size_t)zo * sCo + (size_t)zi * sCi;
    const int row0 = blockIdx.y * 128, col0 = blockIdx.x * NT;

    float acc[4][NTL][4];
    #pragma unroll
    for (int i = 0; i < 4; i++)
        #pragma unroll
        for (int j = 0; j < NTL; j++)
            #pragma unroll
            for (int e = 0; e < 4; e++) acc[i][j][e] = 0.f;

    const int nk = Kd / 32;

    // ---- async stage loader ----
    auto load_stage = [&](int ks, int buf) {
        const int k0 = ks * 32;
        // A: 128x32 floats -> [m][k] pad APAD. 1024 16B-chunks, 4 per thread.
        {
            uint32_t sbase = smw + (uint32_t)buf * ASZ * 4;
            #pragma unroll
            for (int j = 0; j < 4; j++) {
                int idx = tid + 256 * j;
                int r = idx >> 3, c = idx & 7;
                CP_ASYNC16(sbase + (uint32_t)(r * APAD + c * 4) * 4,
                           A + (size_t)(row0 + r) * lda + k0 + c * 4);
            }
        }
        uint32_t bbase = smw + (uint32_t)(2 * ASZ + buf * BSZ) * 4;
        if (TRB) {
            // B: [N,K] rows -> [n][k] pad 36. NT*8 chunks.
            #pragma unroll
            for (int j = 0; j < NT / 32; j++) {
                int idx = tid + 256 * j;
                int r = idx >> 3, c = idx & 7;
                CP_ASYNC16(bbase + (uint32_t)(r * BPAD + c * 4) * 4,
                           B + (size_t)(col0 + r) * ldb + k0 + c * 4);
            }
        } else {
            // B: [K,N] rows -> [k][n] pad NT+8. 32*(NT/4) chunks.
            #pragma unroll
            for (int j = 0; j < NT / 32; j++) {
                int idx = tid + 256 * j;
                int r = idx / (NT / 4), c = idx % (NT / 4);
                CP_ASYNC16(bbase + (uint32_t)(r * BPAD + c * 4) * 4,
                           B + (size_t)(k0 + r) * ldb + col0 + c * 4);
            }
        }
        CP_COMMIT();
    };

    load_stage(0, 0);

    for (int i = 0; i < nk; i++) {
        const int buf = i & 1;
        if (i + 1 < nk) {
            load_stage(i + 1, (i + 1) & 1);
            CP_WAIT1();
        } else {
            CP_WAIT0();
        }
        __syncthreads();

        const uint32_t* Asu = (const uint32_t*)(sm + buf * ASZ);
        const uint32_t* Bsu = (const uint32_t*)(sm + 2 * ASZ + buf * BSZ);

        #pragma unroll
        for (int kt = 0; kt < 4; kt++) {
            uint32_t af[4][4];
            #pragma unroll
            for (int mi = 0; mi < 4; mi++) {
                int rm = wm * 64 + mi * 16 + lq;
                af[mi][0] = Asu[rm * APAD + kt * 8 + lr];
                af[mi][1] = Asu[(rm + 8) * APAD + kt * 8 + lr];
                af[mi][2] = Asu[rm * APAD + kt * 8 + lr + 4];
                af[mi][3] = Asu[(rm + 8) * APAD + kt * 8 + lr + 4];
            }
            uint32_t bf[NTL][2];
            #pragma unroll
            for (int nj = 0; nj < NTL; nj++) {
                int cn = wn * WNT + nj * 8 + lq;
                if (TRB) {
                    bf[nj][0] = Bsu[cn * BPAD + kt * 8 + lr];
                    bf[nj][1] = Bsu[cn * BPAD + kt * 8 + lr + 4];
                } else {
                    bf[nj][0] = Bsu[(kt * 8 + lr) * BPAD + cn];
                    bf[nj][1] = Bsu[(kt * 8 + lr + 4) * BPAD + cn];
                }
            }
            #pragma unroll
            for (int mi = 0; mi < 4; mi++)
                #pragma unroll
                for (int nj = 0; nj < NTL; nj++)
                    mma_tf32_16x8x8(acc[mi][nj], af[mi], bf[nj]);
        }
        __syncthreads();
    }

    // ---- epilogue ----
    #pragma unroll
    for (int mi = 0; mi < 4; mi++) {
        int rg = row0 + wm * 64 + mi * 16 + lq;
        #pragma unroll
        for (int nj = 0; nj < NTL; nj++) {
            int cg = col0 + wn * WNT + nj * 8 + lr * 2;
            float2 v0 = make_float2(acc[mi][nj][0], acc[mi][nj][1]);
            float2 v1 = make_float2(acc[mi][nj][2], acc[mi][nj][3]);
            *(float2*)(C + (size_t)rg * ldc + cg) = v0;
            *(float2*)(C + (size_t)(rg + 8) * ldc + cg) = v1;
        }
    }
}

// ================= small kernels =================
__device__ __forceinline__ float warpSum(float v) {
    #pragma unroll
    for (int o = 16; o; o >>= 1) v += __shfl_xor_sync(0xffffffffu, v, o);
    return v;
}
__device__ __forceinline__ float warpMax(float v) {
    #pragma unroll
    for (int o = 16; o; o >>= 1) v = fmaxf(v, __shfl_xor_sync(0xffffffffu, v, o));
    return v;
}
__device__ __forceinline__ float blockSum(float v, float* sh) {
    int tid = threadIdx.x;
    v = warpSum(v);
    if ((tid & 31) == 0) sh[tid >> 5] = v;
    __syncthreads();
    if (tid == 0) {
        float t = 0.f;
        #pragma unroll
        for (int i = 0; i < 8; i++) t += sh[i];
        sh[0] = t;
    }
    __syncthreads();
    float r = sh[0];
    __syncthreads();
    return r;
}
__device__ __forceinline__ float blockMax(float v, float* sh) {
    int tid = threadIdx.x;
    v = warpMax(v);
    if ((tid & 31) == 0) sh[tid >> 5] = v;
    __syncthreads();
    if (tid == 0) {
        float t = -3.0e38f;
        #pragma unroll
        for (int i = 0; i < 8; i++) t = fmaxf(t, sh[i]);
        sh[0] = t;
    }
    __syncthreads();
    float r = sh[0];
    __syncthreads();
    return r;
}

__global__ void __launch_bounds__(1024) detect_en_k(const int* __restrict__ en32) {
    __shared__ int sh[32];
    int v = en32[threadIdx.x];
    int f = (v & ~1) ? 1 : 0;
    #pragma unroll
    for (int o = 16; o; o >>= 1) f |= __shfl_xor_sync(0xffffffffu, f, o);
    if ((threadIdx.x & 31) == 0) sh[threadIdx.x >> 5] = f;
    __syncthreads();
    if (threadIdx.x == 0) {
        int t = 0;
        #pragma unroll
        for (int i = 0; i < 32; i++) t |= sh[i];
        g_enIsByte = t;
    }
}

__global__ void __launch_bounds__(256) mod_k(const float* __restrict__ t_cond,
                                             const float* __restrict__ adaW,
                                             const float* __restrict__ adab,
                                             float* __restrict__ mod) {
    __shared__ float tc[1024];
    int b  = blockIdx.x / 24;
    int cg = blockIdx.x % 24;
    for (int i = threadIdx.x; i < 1024; i += 256) tc[i] = t_cond[b * 1024 + i];
    __syncthreads();
    int col = cg * 256 + threadIdx.x;
    float acc = adab[col];
    #pragma unroll 4
    for (int i = 0; i < 1024; i++) acc = fmaf(tc[i], adaW[(size_t)i * SIXD + col], acc);
    mod[b * SIXD + col] = acc;
}

__global__ void __launch_bounds__(256) ln_mod_k(const float* __restrict__ x,
                                                const float* __restrict__ w,
                                                const float* __restrict__ mod,
                                                int shOff, int scOff, int useMod,
                                                float* __restrict__ out) {
    __shared__ float sh[8];
    int row = blockIdx.x;
    int b = row >> 10;
    const float* xr = x + (size_t)row * DD;
    int tid = threadIdx.x;
    float v[4];
    float s = 0.f, s2 = 0.f;
    #pragma unroll
    for (int j = 0; j < 4; j++) {
        v[j] = xr[tid + j * 256];
        s += v[j];
        s2 = fmaf(v[j], v[j], s2);
    }
    s  = blockSum(s, sh);
    s2 = blockSum(s2, sh);
    float mu = s * (1.0f / DD);
    float var = s2 * (1.0f / DD) - mu * mu;
    float rs = rsqrtf(var + 1e-5f);
    float* orow = out + (size_t)row * DD;
    #pragma unroll
    for (int j = 0; j < 4; j++) {
        int d = tid + j * 256;
        float y = (v[j] - mu) * rs * w[d];
        if (useMod) y = y * (1.0f + mod[b * SIXD + scOff + d]) + mod[b * SIXD + shOff + d];
        orow[d] = y;
    }
}

__global__ void __launch_bounds__(256) rope_k(float* __restrict__ x,
                                              const float* __restrict__ cosp,
                                              const float* __restrict__ sinp,
                                              int rowStride) {
    int idx = blockIdx.x * 256 + threadIdx.x;
    int d = idx & 31;
    int h = (idx >> 5) & 15;
    int rs = idx >> 9;
    int s = rs & 1023;
    float* p = x + (size_t)rs * rowStride + h * HD + d;
    float x1 = p[0], x2 = p[32];
    float c1 = cosp[s * HD + d],      sn1 = sinp[s * HD + d];
    float c2 = cosp[s * HD + d + 32], sn2 = sinp[s * HD + d + 32];
    p[0]  = x1 * c1 - x2 * sn1;
    p[32] = x2 * c2 + x1 * sn2;
}

__global__ void __launch_bounds__(256) softmax_k(float* __restrict__ sc,
                                                 const int* __restrict__ grp) {
    __shared__ float sh[8];
    int r = blockIdx.x;
    int q = r & 1023;
    int b = r >> 14;
    float* p = sc + (size_t)r * KK;
    int gq = grp[(b << 10) + q];
    int tid = threadIdx.x;
    float v[4];
    float mx = -3.0e38f;
    #pragma unroll
    for (int j = 0; j < 4; j++) {
        int i = tid + j * 256;
        float s = p[i];
        s = (grp[(b << 10) + i] != gq) ? s * INV_SQRT_HD : -1.0e9f;
        v[j] = s;
        mx = fmaxf(mx, s);
    }
    mx = blockMax(mx, sh);
    float sum = 0.f;
    #pragma unroll
    for (int j = 0; j < 4; j++) {
        v[j] = __expf(v[j] - mx);
        sum += v[j];
    }
    sum = blockSum(sum, sh);
    float inv = 1.0f / sum;
    #pragma unroll
    for (int j = 0; j < 4; j++) p[tid + j * 256] = v[j] * inv;
}

__global__ void __launch_bounds__(256) biasgelu_k(float* __restrict__ h1,
                                                  const float* __restrict__ b1) {
    size_t i = (size_t)blockIdx.x * 256 + threadIdx.x;
    float v = h1[i] + b1[i & (MRD - 1)];
    float u = GELU_C * (v + 0.044715f * v * v * v);
    u = fminf(fmaxf(u, -15.f), 15.f);
    float t = __expf(2.0f * u);
    float th = (t - 1.0f) / (t + 1.0f);
    h1[i] = 0.5f * v * (1.0f + th);
}

__global__ void __launch_bounds__(256) resid_k(const float* __restrict__ acc,
                                               const float* __restrict__ base,
                                               const float* __restrict__ bias,
                                               const float* __restrict__ mod,
                                               int goff,
                                               const void* __restrict__ en,
                                               float* __restrict__ out) {
    size_t i = (size_t)blockIdx.x * 256 + threadIdx.x;
    int d = (int)(i & 1023);
    size_t rs = i >> 10;
    int b = (int)(rs >> 10);
    int e = g_enIsByte ? (int)((const unsigned char*)en)[rs]
                       : ((const int*)en)[rs];
    float g = e ? mod[b * SIXD + goff + d] : 0.f;
    float a = acc[i];
    if (bias) a += bias[d];
    out[i] = base[i] + g * a;
}

// ================= host =================
// smem bytes per instantiation (2 stages)
static const int SM_W128 = 2 * (128 * 36 + 32 * 136) * 4;   // 71680  (native, NT=128)
static const int SM_TRB  = 2 * (128 * 36 + 128 * 36) * 4;   // 73728  (TRB,    NT=128)
static const int SM_PV   = 2 * (128 * 36 + 32 * 72) * 4;    // 55296  (native, NT=64)

extern "C" void kernel_launch(void* const* d_in, const int* in_sizes, int n_in,
                              void* d_out, int out_size) {
    const float* q_x    = (const float*)d_in[0];
    const float* kv_x   = (const float*)d_in[1];
    const float* t_cond = (const float*)d_in[2];
    const float* cos_q  = (const float*)d_in[3];
    const float* sin_q  = (const float*)d_in[4];
    const float* cos_k  = (const float*)d_in[5];
    const float* sin_k  = (const float*)d_in[6];
    const int*   grp    = (const int*)d_in[7];
    const void*  en     = d_in[8];
    const float* qn_w   = (const float*)d_in[9];
    const float* kvn_w  = (const float*)d_in[10];
    const float* n2_w   = (const float*)d_in[11];
    const float* Wq     = (const float*)d_in[12];
    const float* Wkv    = (const float*)d_in[13];
    const float* Wo     = (const float*)d_in[14];
    const float* W1     = (const float*)d_in[15];
    const float* b1     = (const float*)d_in[16];
    const float* W2     = (const float*)d_in[17];
    const float* b2     = (const float*)d_in[18];
    const float* adaW   = (const float*)d_in[19];
    const float* adab   = (const float*)d_in[20];
    float* out = (float*)d_out;

    float *mod, *qn, *kvn, *q, *kv, *scores, *attn, *x, *h, *h1, *h2;
    cudaGetSymbolAddress((void**)&mod,    g_mod);
    cudaGetSymbolAddress((void**)&qn,     g_qn);
    cudaGetSymbolAddress((void**)&kvn,    g_kvn);
    cudaGetSymbolAddress((void**)&q,      g_q);
    cudaGetSymbolAddress((void**)&kv,     g_kv);
    cudaGetSymbolAddress((void**)&scores, g_scores);
    cudaGetSymbolAddress((void**)&attn,   g_attn);
    cudaGetSymbolAddress((void**)&x,      g_x);
    cudaGetSymbolAddress((void**)&h,      g_h);
    cudaGetSymbolAddress((void**)&h1,     g_h1);
    cudaGetSymbolAddress((void**)&h2,     g_h2);

    cudaFuncSetAttribute(gemm_mma<128, false>,
                         cudaFuncAttributeMaxDynamicSharedMemorySize, SM_W128);
    cudaFuncSetAttribute(gemm_mma<128, true>,
                         cudaFuncAttributeMaxDynamicSharedMemorySize, SM_TRB);
    cudaFuncSetAttribute(gemm_mma<64, false>,
                         cudaFuncAttributeMaxDynamicSharedMemorySize, SM_PV);

    // 0. detect query_enabled dtype
    detect_en_k<<<1, 1024>>>((const int*)en);

    // 1. adaLN modulation
    mod_k<<<BB * (SIXD / 256), 256>>>(t_cond, adaW, adab, mod);

    // 2. LayerNorms
    ln_mod_k<<<NBS, 256>>>(q_x, qn_w, mod, 0, DD, 1, qn);
    ln_mod_k<<<NBS, 256>>>(kv_x, kvn_w, mod, 0, 0, 0, kvn);

    // 3. Projections
    gemm_mma<128, false><<<dim3(8, 32, 1), 256, SM_W128>>>(
        qn, Wq, q, DD, DD, DD, DD, 0, 0, 0, 0, 0, 0, 1);
    gemm_mma<128, false><<<dim3(16, 32, 1), 256, SM_W128>>>(
        kvn, Wkv, kv, DD, DD, 2 * DD, 2 * DD, 0, 0, 0, 0, 0, 0, 1);

    // 4. RoPE
    rope_k<<<(NBS * HH * 32) / 256, 256>>>(q, cos_q, sin_q, DD);
    rope_k<<<(NBS * HH * 32) / 256, 256>>>(kv, cos_k, sin_k, 2 * DD);

    // 5. scores[b,h] = Q_bh @ K_bh^T   (B = K-matrix [token, hd] -> TRB)
    gemm_mma<128, true><<<dim3(8, 8, BB * HH), 256, SM_TRB>>>(
        q, kv, scores, HD, DD, 2 * DD, KK,
        (long long)SS * DD, HD,
        (long long)KK * 2 * DD, HD,
        (long long)HH * SS * KK, (long long)SS * KK, HH);

    // 6. scale + mask + softmax
    softmax_k<<<BB * HH * SS, 256>>>(scores, grp);

    // 7. attn[b,h] = P @ V_bh  (V native [token, hd] = [K,N])
    gemm_mma<64, false><<<dim3(1, 8, BB * HH), 256, SM_PV>>>(
        scores, kv + DD, attn, KK, KK, 2 * DD, DD,
        (long long)HH * SS * KK, (long long)SS * KK,
        (long long)KK * 2 * DD, HD,
        (long long)SS * DD, HD, HH);

    // 8. attn @ Wo, gated residual -> x
    gemm_mma<128, false><<<dim3(8, 32, 1), 256, SM_W128>>>(
        attn, Wo, h2, DD, DD, DD, DD, 0, 0, 0, 0, 0, 0, 1);
    resid_k<<<(NBS * DD) / 256, 256>>>(h2, q_x, nullptr, mod, 2 * DD, en, x);

    // 9. LN + mlp modulation
    ln_mod_k<<<NBS, 256>>>(x, n2_w, mod, 3 * DD, 4 * DD, 1, h);

    // 10. MLP
    gemm_mma<128, false><<<dim3(32, 32, 1), 256, SM_W128>>>(
        h, W1, h1, DD, DD, MRD, MRD, 0, 0, 0, 0, 0, 0, 1);
    biasgelu_k<<<(int)(((size_t)NBS * MRD) / 256), 256>>>(h1, b1);
    gemm_mma<128, false><<<dim3(8, 32, 1), 256, SM_W128>>>(
        h1, W2, h2, MRD, MRD, DD, DD, 0, 0, 0, 0, 0, 0, 1);

    // 11. final gated residual -> out
    resid_k<<<(NBS * DD) / 256, 256>>>(h2, x, b2, mod, 5 * DD, en, out);
}

// round 6
// speedup vs baseline: 3.6002x; 1.2067x over previous
#include <cuda_runtime.h>
#include <cstdint>

// Problem constants
#define BB 4
#define SS 1024
#define KK 1024
#define DD 1024
#define HH 16
#define HD 64
#define MRD 4096          // MR * D
#define SIXD 6144
#define NBS 4096          // B * S  (== B * K)
#define INV_SQRT_HD 0.125f
#define GELU_C 0.7978845608028654f

// ---------------- scratch (static device globals; no allocation) ----------------
__device__ float g_mod[BB * SIXD];
__device__ float g_qn[NBS * DD];
__device__ float g_kvn[NBS * DD];
__device__ float g_q[NBS * DD];
__device__ float g_kv[NBS * 2 * DD];
__device__ float g_attn[NBS * DD];
__device__ float g_x[NBS * DD];
__device__ float g_h[NBS * DD];
__device__ float g_h1[(size_t)NBS * MRD];               // 64MB
__device__ int   g_enIsByte;

// ================= PTX helpers (sm_80-safe only) =================
__device__ __forceinline__ uint32_t smem_u32(const void* p) {
    uint32_t a;
    asm("{ .reg .u64 t; cvta.to.shared.u64 t, %1; cvt.u32.u64 %0, t; }" : "=r"(a) : "l"(p));
    return a;
}
#define CP_ASYNC16(sa, ga) \
    asm volatile("cp.async.ca.shared.global [%0], [%1], 16;" :: "r"(sa), "l"(ga) : "memory")
#define CP_COMMIT() asm volatile("cp.async.commit_group;" ::: "memory")
#define CP_WAIT0()  asm volatile("cp.async.wait_group 0;" ::: "memory")
#define CP_WAIT1()  asm volatile("cp.async.wait_group 1;" ::: "memory")

__device__ __forceinline__ void mma_tf32_16x8x8(float* c, const uint32_t* a, const uint32_t* b) {
    asm volatile(
        "mma.sync.aligned.m16n8k8.row.col.f32.tf32.tf32.f32 "
        "{%0,%1,%2,%3}, {%4,%5,%6,%7}, {%8,%9}, {%0,%1,%2,%3};"
        : "+f"(c[0]), "+f"(c[1]), "+f"(c[2]), "+f"(c[3])
        : "r"(a[0]), "r"(a[1]), "r"(a[2]), "r"(a[3]), "r"(b[0]), "r"(b[1]));
}
__device__ __forceinline__ uint32_t tf32rna(float f) {
    uint32_t o;
    asm("cvt.rna.tf32.f32 %0, %1;" : "=r"(o) : "f"(f));
    return o;
}
__device__ __forceinline__ float gelu_f(float v) {
    float u = GELU_C * (v + 0.044715f * v * v * v);
    u = fminf(fmaxf(u, -15.f), 15.f);
    float t = __expf(2.0f * u);
    float th = (t - 1.0f) / (t + 1.0f);
    return 0.5f * v * (1.0f + th);
}

// ================= mma.sync tf32 GEMM, fused epilogues =================
// C[M,N] = A[M,K] @ B[K,N], all row-major fp32. CTA tile 128x128, BK=32,
// 8 warps (2x4), 2-stage cp.async pipeline.
// EPI: 0 = plain store; 1 = gelu(acc + bias[col]); 2 = gated residual:
//      out = base + (en[row] ? mod[(row>>10)*SIXD + goff + col] : 0) * (acc (+bias[col]))
template <int EPI>
__global__ void __launch_bounds__(256) gemm_mma(
    const float* __restrict__ A, const float* __restrict__ B, float* __restrict__ C,
    int Kd, int lda, int ldb, int ldc,
    const float* __restrict__ bias, const float* __restrict__ modv, int goff,
    const void* __restrict__ en, const float* __restrict__ basep)
{
    constexpr int APAD = 36;
    constexpr int ASZ  = 128 * APAD;
    constexpr int BPAD = 136;
    constexpr int BSZ  = 32 * BPAD;

    extern __shared__ float sm[];
    uint32_t smw = smem_u32(sm);

    const int tid = threadIdx.x;
    const int lane = tid & 31;
    const int wid = tid >> 5;
    const int wm = wid >> 2;
    const int wn = wid & 3;
    const int lq = lane >> 2;
    const int lr = lane & 3;

    const int row0 = blockIdx.y * 128, col0 = blockIdx.x * 128;

    float acc[4][4][4];
    #pragma unroll
    for (int i = 0; i < 4; i++)
        #pragma unroll
        for (int j = 0; j < 4; j++)
            #pragma unroll
            for (int e = 0; e < 4; e++) acc[i][j][e] = 0.f;

    const int nk = Kd / 32;

    auto load_stage = [&](int ks, int buf) {
        const int k0 = ks * 32;
        uint32_t sbase = smw + (uint32_t)buf * ASZ * 4;
        #pragma unroll
        for (int j = 0; j < 4; j++) {
            int idx = tid + 256 * j;
            int r = idx >> 3, c = idx & 7;
            CP_ASYNC16(sbase + (uint32_t)(r * APAD + c * 4) * 4,
                       A + (size_t)(row0 + r) * lda + k0 + c * 4);
        }
        uint32_t bbase = smw + (uint32_t)(2 * ASZ + buf * BSZ) * 4;
        #pragma unroll
        for (int j = 0; j < 4; j++) {
            int idx = tid + 256 * j;
            int r = idx >> 5, c = idx & 31;
            CP_ASYNC16(bbase + (uint32_t)(r * BPAD + c * 4) * 4,
                       B + (size_t)(k0 + r) * ldb + col0 + c * 4);
        }
        CP_COMMIT();
    };

    load_stage(0, 0);

    for (int i = 0; i < nk; i++) {
        const int buf = i & 1;
        if (i + 1 < nk) { load_stage(i + 1, (i + 1) & 1); CP_WAIT1(); }
        else CP_WAIT0();
        __syncthreads();

        const uint32_t* Asu = (const uint32_t*)(sm + buf * ASZ);
        const uint32_t* Bsu = (const uint32_t*)(sm + 2 * ASZ + buf * BSZ);

        #pragma unroll
        for (int kt = 0; kt < 4; kt++) {
            uint32_t af[4][4];
            #pragma unroll
            for (int mi = 0; mi < 4; mi++) {
                int rm = wm * 64 + mi * 16 + lq;
                af[mi][0] = Asu[rm * APAD + kt * 8 + lr];
                af[mi][1] = Asu[(rm + 8) * APAD + kt * 8 + lr];
                af[mi][2] = Asu[rm * APAD + kt * 8 + lr + 4];
                af[mi][3] = Asu[(rm + 8) * APAD + kt * 8 + lr + 4];
            }
            uint32_t bf[4][2];
            #pragma unroll
            for (int nj = 0; nj < 4; nj++) {
                int cn = wn * 32 + nj * 8 + lq;
                bf[nj][0] = Bsu[(kt * 8 + lr) * BPAD + cn];
                bf[nj][1] = Bsu[(kt * 8 + lr + 4) * BPAD + cn];
            }
            #pragma unroll
            for (int mi = 0; mi < 4; mi++)
                #pragma unroll
                for (int nj = 0; nj < 4; nj++)
                    mma_tf32_16x8x8(acc[mi][nj], af[mi], bf[nj]);
        }
        __syncthreads();
    }

    // ---- epilogue ----
    #pragma unroll
    for (int mi = 0; mi < 4; mi++) {
        int rg = row0 + wm * 64 + mi * 16 + lq;
        float g0 = 0.f, g1 = 0.f;
        if (EPI == 2) {
            int e0 = g_enIsByte ? (int)((const unsigned char*)en)[rg]
                                : ((const int*)en)[rg];
            int e1 = g_enIsByte ? (int)((const unsigned char*)en)[rg + 8]
                                : ((const int*)en)[rg + 8];
            g0 = e0 ? 1.f : 0.f;
            g1 = e1 ? 1.f : 0.f;
        }
        #pragma unroll
        for (int nj = 0; nj < 4; nj++) {
            int cg = col0 + wn * 32 + nj * 8 + lr * 2;
            float v[4] = {acc[mi][nj][0], acc[mi][nj][1], acc[mi][nj][2], acc[mi][nj][3]};
            if (EPI == 1) {
                float b0 = bias[cg], b1v = bias[cg + 1];
                v[0] = gelu_f(v[0] + b0); v[1] = gelu_f(v[1] + b1v);
                v[2] = gelu_f(v[2] + b0); v[3] = gelu_f(v[3] + b1v);
            } else if (EPI == 2) {
                float b0 = bias ? bias[cg] : 0.f, b1v = bias ? bias[cg + 1] : 0.f;
                int bb0 = rg >> 10, bb1 = (rg + 8) >> 10;
                float m00 = modv[bb0 * SIXD + goff + cg];
                float m01 = modv[bb0 * SIXD + goff + cg + 1];
                float m10 = modv[bb1 * SIXD + goff + cg];
                float m11 = modv[bb1 * SIXD + goff + cg + 1];
                v[0] = basep[(size_t)rg * DD + cg]       + g0 * m00 * (v[0] + b0);
                v[1] = basep[(size_t)rg * DD + cg + 1]   + g0 * m01 * (v[1] + b1v);
                v[2] = basep[(size_t)(rg + 8) * DD + cg] + g1 * m10 * (v[2] + b0);
                v[3] = basep[(size_t)(rg + 8) * DD + cg + 1] + g1 * m11 * (v[3] + b1v);
            }
            *(float2*)(C + (size_t)rg * ldc + cg) = make_float2(v[0], v[1]);
            *(float2*)(C + (size_t)(rg + 8) * ldc + cg) = make_float2(v[2], v[3]);
        }
    }
}

// ================= flash attention (tf32 mma, fused mask+softmax) =================
// Grid: (S/128, B*H). 256 threads, 8 warps; warp w owns q-rows w*16..w*16+15.
// SMEM floats: Qs[128][68] @0, Ks[128][68] @8704, Vs[128][72] @17408,
//              Ps[128][132] @26624, grpq[128] @43520, grpk[128] @43648.
#define FL_QP 68
#define FL_VP 72
#define FL_PP 132
#define FL_KOFF 8704
#define FL_VOFF 17408
#define FL_POFF 26624
#define FL_GQ 43520
#define FL_GK 43648
#define FL_SMEM ((43648 + 128) * 4)

__global__ void __launch_bounds__(256) flash_k(
    const float* __restrict__ q, const float* __restrict__ kv,
    const int* __restrict__ grp, float* __restrict__ attn)
{
    extern __shared__ float sm[];
    uint32_t smw = smem_u32(sm);
    int* grpq = (int*)(sm + FL_GQ);
    int* grpk = (int*)(sm + FL_GK);

    const int tid = threadIdx.x;
    const int lane = tid & 31;
    const int wid = tid >> 5;
    const int wr0 = wid * 16;
    const int lq = lane >> 2;
    const int lr = lane & 3;

    const int qb = blockIdx.x;
    const int b = blockIdx.y >> 4;
    const int h = blockIdx.y & 15;

    // ---- load Q tile (cp.async) + grpq ----
    #pragma unroll
    for (int j = 0; j < 8; j++) {
        int idx = tid + 256 * j;
        int r = idx >> 4, c = (idx & 15) << 2;
        CP_ASYNC16(smw + (uint32_t)(r * FL_QP + c) * 4,
                   q + (size_t)(b * SS + qb * 128 + r) * DD + h * HD + c);
    }
    CP_COMMIT();
    if (tid < 128) grpq[tid] = grp[b * 1024 + qb * 128 + tid];

    float m0 = -3.0e38f, m1 = -3.0e38f, l0 = 0.f, l1 = 0.f;
    float oacc[8][4];
    #pragma unroll
    for (int j = 0; j < 8; j++)
        #pragma unroll
        for (int e = 0; e < 4; e++) oacc[j][e] = 0.f;

    for (int kc = 0; kc < 8; kc++) {
        // ---- load K,V chunk + grpk ----
        #pragma unroll
        for (int j = 0; j < 8; j++) {
            int idx = tid + 256 * j;
            int r = idx >> 4, c = (idx & 15) << 2;
            const float* src = kv + (size_t)(b * 1024 + kc * 128 + r) * (2 * DD) + h * HD + c;
            CP_ASYNC16(smw + (uint32_t)(FL_KOFF + r * FL_QP + c) * 4, src);
            CP_ASYNC16(smw + (uint32_t)(FL_VOFF + r * FL_VP + c) * 4, src + DD);
        }
        CP_COMMIT();
        if (tid < 128) grpk[tid] = grp[b * 1024 + kc * 128 + tid];
        CP_WAIT0();
        __syncthreads();

        // ---- S = Q @ K^T : warp tile 16 x 128 ----
        float sacc[16][4];
        #pragma unroll
        for (int nj = 0; nj < 16; nj++)
            #pragma unroll
            for (int e = 0; e < 4; e++) sacc[nj][e] = 0.f;

        const uint32_t* Qs = (const uint32_t*)sm;
        const uint32_t* Ks = (const uint32_t*)(sm + FL_KOFF);
        const uint32_t* Vs = (const uint32_t*)(sm + FL_VOFF);

        #pragma unroll
        for (int kt = 0; kt < 8; kt++) {
            uint32_t af[4];
            af[0] = Qs[(wr0 + lq) * FL_QP + kt * 8 + lr];
            af[1] = Qs[(wr0 + lq + 8) * FL_QP + kt * 8 + lr];
            af[2] = Qs[(wr0 + lq) * FL_QP + kt * 8 + lr + 4];
            af[3] = Qs[(wr0 + lq + 8) * FL_QP + kt * 8 + lr + 4];
            #pragma unroll
            for (int nj = 0; nj < 16; nj++) {
                uint32_t bf[2];
                bf[0] = Ks[(nj * 8 + lq) * FL_QP + kt * 8 + lr];
                bf[1] = Ks[(nj * 8 + lq) * FL_QP + kt * 8 + lr + 4];
                mma_tf32_16x8x8(sacc[nj], af, bf);
            }
        }

        // ---- scale + mask + running softmax ----
        int gq0 = grpq[wr0 + lq], gq1 = grpq[wr0 + lq + 8];
        float rm0 = -3.0e38f, rm1 = -3.0e38f;
        #pragma unroll
        for (int nj = 0; nj < 16; nj++) {
            int c0i = nj * 8 + 2 * lr;
            int gk0 = grpk[c0i], gk1 = grpk[c0i + 1];
            float s0 = (gk0 != gq0) ? sacc[nj][0] * INV_SQRT_HD : -1.0e9f;
            float s1 = (gk1 != gq0) ? sacc[nj][1] * INV_SQRT_HD : -1.0e9f;
            float s2 = (gk0 != gq1) ? sacc[nj][2] * INV_SQRT_HD : -1.0e9f;
            float s3 = (gk1 != gq1) ? sacc[nj][3] * INV_SQRT_HD : -1.0e9f;
            sacc[nj][0] = s0; sacc[nj][1] = s1; sacc[nj][2] = s2; sacc[nj][3] = s3;
            rm0 = fmaxf(rm0, fmaxf(s0, s1));
            rm1 = fmaxf(rm1, fmaxf(s2, s3));
        }
        rm0 = fmaxf(rm0, __shfl_xor_sync(0xffffffffu, rm0, 1));
        rm0 = fmaxf(rm0, __shfl_xor_sync(0xffffffffu, rm0, 2));
        rm1 = fmaxf(rm1, __shfl_xor_sync(0xffffffffu, rm1, 1));
        rm1 = fmaxf(rm1, __shfl_xor_sync(0xffffffffu, rm1, 2));
        float mn0 = fmaxf(m0, rm0), mn1 = fmaxf(m1, rm1);
        float al0 = __expf(m0 - mn0), al1 = __expf(m1 - mn1);

        float ps0 = 0.f, ps1 = 0.f;
        #pragma unroll
        for (int nj = 0; nj < 16; nj++) {
            sacc[nj][0] = __expf(sacc[nj][0] - mn0);
            sacc[nj][1] = __expf(sacc[nj][1] - mn0);
            sacc[nj][2] = __expf(sacc[nj][2] - mn1);
            sacc[nj][3] = __expf(sacc[nj][3] - mn1);
            ps0 += sacc[nj][0] + sacc[nj][1];
            ps1 += sacc[nj][2] + sacc[nj][3];
        }
        ps0 += __shfl_xor_sync(0xffffffffu, ps0, 1);
        ps0 += __shfl_xor_sync(0xffffffffu, ps0, 2);
        ps1 += __shfl_xor_sync(0xffffffffu, ps1, 1);
        ps1 += __shfl_xor_sync(0xffffffffu, ps1, 2);
        l0 = l0 * al0 + ps0;
        l1 = l1 * al1 + ps1;
        m0 = mn0; m1 = mn1;

        #pragma unroll
        for (int nj = 0; nj < 8; nj++) {
            oacc[nj][0] *= al0; oacc[nj][1] *= al0;
            oacc[nj][2] *= al1; oacc[nj][3] *= al1;
        }

        // ---- write P (tf32) to per-warp SMEM region ----
        uint32_t* Ps = (uint32_t*)(sm + FL_POFF);
        #pragma unroll
        for (int nj = 0; nj < 16; nj++) {
            int c0i = nj * 8 + 2 * lr;
            Ps[(wr0 + lq) * FL_PP + c0i]     = tf32rna(sacc[nj][0]);
            Ps[(wr0 + lq) * FL_PP + c0i + 1] = tf32rna(sacc[nj][1]);
            Ps[(wr0 + lq + 8) * FL_PP + c0i]     = tf32rna(sacc[nj][2]);
            Ps[(wr0 + lq + 8) * FL_PP + c0i + 1] = tf32rna(sacc[nj][3]);
        }
        __syncwarp();

        // ---- O += P @ V ----
        #pragma unroll
        for (int kt = 0; kt < 16; kt++) {
            uint32_t af[4];
            af[0] = Ps[(wr0 + lq) * FL_PP + kt * 8 + lr];
            af[1] = Ps[(wr0 + lq + 8) * FL_PP + kt * 8 + lr];
            af[2] = Ps[(wr0 + lq) * FL_PP + kt * 8 + lr + 4];
            af[3] = Ps[(wr0 + lq + 8) * FL_PP + kt * 8 + lr + 4];
            #pragma unroll
            for (int nj = 0; nj < 8; nj++) {
                uint32_t bf[2];
                bf[0] = Vs[(kt * 8 + lr) * FL_VP + nj * 8 + lq];
                bf[1] = Vs[(kt * 8 + lr + 4) * FL_VP + nj * 8 + lq];
                mma_tf32_16x8x8(oacc[nj], af, bf);
            }
        }
        __syncthreads();
    }

    // ---- finalize ----
    float il0 = 1.0f / l0, il1 = 1.0f / l1;
    int r0 = b * 1024 + qb * 128 + wr0 + lq;
    #pragma unroll
    for (int nj = 0; nj < 8; nj++) {
        int cg = h * HD + nj * 8 + 2 * lr;
        *(float2*)(attn + (size_t)r0 * DD + cg) =
            make_float2(oacc[nj][0] * il0, oacc[nj][1] * il0);
        *(float2*)(attn + (size_t)(r0 + 8) * DD + cg) =
            make_float2(oacc[nj][2] * il1, oacc[nj][3] * il1);
    }
}

// ================= small kernels =================
__device__ __forceinline__ float warpSum(float v) {
    #pragma unroll
    for (int o = 16; o; o >>= 1) v += __shfl_xor_sync(0xffffffffu, v, o);
    return v;
}
__device__ __forceinline__ float blockSum(float v, float* sh) {
    int tid = threadIdx.x;
    v = warpSum(v);
    if ((tid & 31) == 0) sh[tid >> 5] = v;
    __syncthreads();
    if (tid == 0) {
        float t = 0.f;
        #pragma unroll
        for (int i = 0; i < 8; i++) t += sh[i];
        sh[0] = t;
    }
    __syncthreads();
    float r = sh[0];
    __syncthreads();
    return r;
}

__global__ void __launch_bounds__(1024) detect_en_k(const int* __restrict__ en32) {
    __shared__ int sh[32];
    int v = en32[threadIdx.x];
    int f = (v & ~1) ? 1 : 0;
    #pragma unroll
    for (int o = 16; o; o >>= 1) f |= __shfl_xor_sync(0xffffffffu, f, o);
    if ((threadIdx.x & 31) == 0) sh[threadIdx.x >> 5] = f;
    __syncthreads();
    if (threadIdx.x == 0) {
        int t = 0;
        #pragma unroll
        for (int i = 0; i < 32; i++) t |= sh[i];
        g_enIsByte = t;
    }
}

__global__ void __launch_bounds__(256) mod_k(const float* __restrict__ t_cond,
                                             const float* __restrict__ adaW,
                                             const float* __restrict__ adab,
                                             float* __restrict__ mod) {
    __shared__ float tc[1024];
    int b  = blockIdx.x / 24;
    int cg = blockIdx.x % 24;
    for (int i = threadIdx.x; i < 1024; i += 256) tc[i] = t_cond[b * 1024 + i];
    __syncthreads();
    int col = cg * 256 + threadIdx.x;
    float acc = adab[col];
    #pragma unroll 4
    for (int i = 0; i < 1024; i++) acc = fmaf(tc[i], adaW[(size_t)i * SIXD + col], acc);
    mod[b * SIXD + col] = acc;
}

__global__ void __launch_bounds__(256) ln_mod_k(const float* __restrict__ x,
                                                const float* __restrict__ w,
                                                const float* __restrict__ mod,
                                                int shOff, int scOff, int useMod,
                                                float* __restrict__ out) {
    __shared__ float sh[8];
    int row = blockIdx.x;
    int b = row >> 10;
    const float* xr = x + (size_t)row * DD;
    int tid = threadIdx.x;
    float v[4];
    float s = 0.f, s2 = 0.f;
    #pragma unroll
    for (int j = 0; j < 4; j++) {
        v[j] = xr[tid + j * 256];
        s += v[j];
        s2 = fmaf(v[j], v[j], s2);
    }
    s  = blockSum(s, sh);
    s2 = blockSum(s2, sh);
    float mu = s * (1.0f / DD);
    float var = s2 * (1.0f / DD) - mu * mu;
    float rs = rsqrtf(var + 1e-5f);
    float* orow = out + (size_t)row * DD;
    #pragma unroll
    for (int j = 0; j < 4; j++) {
        int d = tid + j * 256;
        float y = (v[j] - mu) * rs * w[d];
        if (useMod) y = y * (1.0f + mod[b * SIXD + scOff + d]) + mod[b * SIXD + shOff + d];
        orow[d] = y;
    }
}

__global__ void __launch_bounds__(256) rope_k(float* __restrict__ x,
                                              const float* __restrict__ cosp,
                                              const float* __restrict__ sinp,
                                              int rowStride) {
    int idx = blockIdx.x * 256 + threadIdx.x;
    int d = idx & 31;
    int h = (idx >> 5) & 15;
    int rs = idx >> 9;
    int s = rs & 1023;
    float* p = x + (size_t)rs * rowStride + h * HD + d;
    float x1 = p[0], x2 = p[32];
    float c1 = cosp[s * HD + d],      sn1 = sinp[s * HD + d];
    float c2 = cosp[s * HD + d + 32], sn2 = sinp[s * HD + d + 32];
    p[0]  = x1 * c1 - x2 * sn1;
    p[32] = x2 * c2 + x1 * sn2;
}

// ================= host =================
static const int SM_GEMM = 2 * (128 * 36 + 32 * 136) * 4;   // 71680

extern "C" void kernel_launch(void* const* d_in, const int* in_sizes, int n_in,
                              void* d_out, int out_size) {
    const float* q_x    = (const float*)d_in[0];
    const float* kv_x   = (const float*)d_in[1];
    const float* t_cond = (const float*)d_in[2];
    const float* cos_q  = (const float*)d_in[3];
    const float* sin_q  = (const float*)d_in[4];
    const float* cos_k  = (const float*)d_in[5];
    const float* sin_k  = (const float*)d_in[6];
    const int*   grp    = (const int*)d_in[7];
    const void*  en     = d_in[8];
    const float* qn_w   = (const float*)d_in[9];
    const float* kvn_w  = (const float*)d_in[10];
    const float* n2_w   = (const float*)d_in[11];
    const float* Wq     = (const float*)d_in[12];
    const float* Wkv    = (const float*)d_in[13];
    const float* Wo     = (const float*)d_in[14];
    const float* W1     = (const float*)d_in[15];
    const float* b1     = (const float*)d_in[16];
    const float* W2     = (const float*)d_in[17];
    const float* b2     = (const float*)d_in[18];
    const float* adaW   = (const float*)d_in[19];
    const float* adab   = (const float*)d_in[20];
    float* out = (float*)d_out;

    float *mod, *qn, *kvn, *q, *kv, *attn, *x, *h, *h1;
    cudaGetSymbolAddress((void**)&mod,  g_mod);
    cudaGetSymbolAddress((void**)&qn,   g_qn);
    cudaGetSymbolAddress((void**)&kvn,  g_kvn);
    cudaGetSymbolAddress((void**)&q,    g_q);
    cudaGetSymbolAddress((void**)&kv,   g_kv);
    cudaGetSymbolAddress((void**)&attn, g_attn);
    cudaGetSymbolAddress((void**)&x,    g_x);
    cudaGetSymbolAddress((void**)&h,    g_h);
    cudaGetSymbolAddress((void**)&h1,   g_h1);

    cudaFuncSetAttribute(gemm_mma<0>, cudaFuncAttributeMaxDynamicSharedMemorySize, SM_GEMM);
    cudaFuncSetAttribute(gemm_mma<1>, cudaFuncAttributeMaxDynamicSharedMemorySize, SM_GEMM);
    cudaFuncSetAttribute(gemm_mma<2>, cudaFuncAttributeMaxDynamicSharedMemorySize, SM_GEMM);
    cudaFuncSetAttribute(flash_k, cudaFuncAttributeMaxDynamicSharedMemorySize, FL_SMEM);

    // 0. detect query_enabled dtype
    detect_en_k<<<1, 1024>>>((const int*)en);

    // 1. adaLN modulation
    mod_k<<<BB * (SIXD / 256), 256>>>(t_cond, adaW, adab, mod);

    // 2. LayerNorms
    ln_mod_k<<<NBS, 256>>>(q_x, qn_w, mod, 0, DD, 1, qn);
    ln_mod_k<<<NBS, 256>>>(kv_x, kvn_w, mod, 0, 0, 0, kvn);

    // 3. Projections
    gemm_mma<0><<<dim3(8, 32), 256, SM_GEMM>>>(
        qn, Wq, q, DD, DD, DD, DD, nullptr, nullptr, 0, nullptr, nullptr);
    gemm_mma<0><<<dim3(16, 32), 256, SM_GEMM>>>(
        kvn, Wkv, kv, DD, DD, 2 * DD, 2 * DD, nullptr, nullptr, 0, nullptr, nullptr);

    // 4. RoPE
    rope_k<<<(NBS * HH * 32) / 256, 256>>>(q, cos_q, sin_q, DD);
    rope_k<<<(NBS * HH * 32) / 256, 256>>>(kv, cos_k, sin_k, 2 * DD);

    // 5. fused attention (scores + mask + softmax + PV)
    flash_k<<<dim3(SS / 128, BB * HH), 256, FL_SMEM>>>(q, kv, grp, attn);

    // 6. attn @ Wo + gated residual -> x
    gemm_mma<2><<<dim3(8, 32), 256, SM_GEMM>>>(
        attn, Wo, x, DD, DD, DD, DD, nullptr, mod, 2 * DD, en, q_x);

    // 7. LN + mlp modulation
    ln_mod_k<<<NBS, 256>>>(x, n2_w, mod, 3 * DD, 4 * DD, 1, h);

    // 8. MLP: W1 + bias + gelu fused, then W2 + bias + gated residual fused
    gemm_mma<1><<<dim3(32, 32), 256, SM_GEMM>>>(
        h, W1, h1, DD, DD, MRD, MRD, b1, nullptr, 0, nullptr, nullptr);
    gemm_mma<2><<<dim3(8, 32), 256, SM_GEMM>>>(
        h1, W2, out, MRD, MRD, DD, DD, b2, mod, 5 * DD, en, x);
}

// round 7
// speedup vs baseline: 5.3346x; 1.4818x over previous
#include <cuda_runtime.h>
#include <cuda_fp16.h>
#include <cstdint>

// Problem constants
#define BB 4
#define SS 1024
#define KK 1024
#define DD 1024
#define HH 16
#define HD 64
#define MRD 4096
#define SIXD 6144
#define NBS 4096
#define INV_SQRT_HD 0.125f
#define GELU_C 0.7978845608028654f

// ---------------- scratch ----------------
__device__ float  g_mod[BB * SIXD];
__device__ float  g_x[NBS * DD];
__device__ __half g_qn_h[NBS * DD];
__device__ __half g_kvn_h[NBS * DD];
__device__ __half g_q_h[NBS * DD];
__device__ __half g_kv_h[NBS * 2 * DD];
__device__ __half g_attn_h[NBS * DD];
__device__ __half g_hh[NBS * DD];
__device__ __half g_h1_h[(size_t)NBS * MRD];
__device__ __half g_wq_h[DD * DD];
__device__ __half g_wkv_h[DD * 2 * DD];
__device__ __half g_wo_h[DD * DD];
__device__ __half g_w1_h[DD * MRD];
__device__ __half g_w2_h[MRD * DD];
__device__ int    g_enIsByte;

// ================= PTX helpers =================
__device__ __forceinline__ uint32_t smem_u32(const void* p) {
    uint32_t a;
    asm("{ .reg .u64 t; cvta.to.shared.u64 t, %1; cvt.u32.u64 %0, t; }" : "=r"(a) : "l"(p));
    return a;
}
#define CP_ASYNC16(sa, ga) \
    asm volatile("cp.async.ca.shared.global [%0], [%1], 16;" :: "r"(sa), "l"(ga) : "memory")
#define CP_COMMIT() asm volatile("cp.async.commit_group;" ::: "memory")
#define CP_WAIT0()  asm volatile("cp.async.wait_group 0;" ::: "memory")
#define CP_WAIT1()  asm volatile("cp.async.wait_group 1;" ::: "memory")

#define LDSM_X4(d0, d1, d2, d3, addr)                                          \
    asm volatile("ldmatrix.sync.aligned.m8n8.x4.shared.b16 {%0,%1,%2,%3}, [%4];" \
        : "=r"(d0), "=r"(d1), "=r"(d2), "=r"(d3) : "r"(addr))
#define LDSM_X4_T(d0, d1, d2, d3, addr)                                        \
    asm volatile("ldmatrix.sync.aligned.m8n8.x4.trans.shared.b16 {%0,%1,%2,%3}, [%4];" \
        : "=r"(d0), "=r"(d1), "=r"(d2), "=r"(d3) : "r"(addr))

__device__ __forceinline__ void mma_f16(float* c, uint32_t a0, uint32_t a1,
                                        uint32_t a2, uint32_t a3,
                                        uint32_t b0, uint32_t b1) {
    asm volatile(
        "mma.sync.aligned.m16n8k16.row.col.f32.f16.f16.f32 "
        "{%0,%1,%2,%3}, {%4,%5,%6,%7}, {%8,%9}, {%0,%1,%2,%3};"
        : "+f"(c[0]), "+f"(c[1]), "+f"(c[2]), "+f"(c[3])
        : "r"(a0), "r"(a1), "r"(a2), "r"(a3), "r"(b0), "r"(b1));
}
__device__ __forceinline__ float gelu_f(float v) {
    float u = GELU_C * (v + 0.044715f * v * v * v);
    u = fminf(fmaxf(u, -15.f), 15.f);
    float t = __expf(2.0f * u);
    return 0.5f * v * (1.0f + (t - 1.0f) / (t + 1.0f));
}

// ================= fp16 mma GEMM, 3-stage cp.async, ldmatrix =================
// C[M,N] = A[M,K] @ B[K,N]; A,B fp16 row-major. CTA 128x128, BK=32 (2 k16 steps).
// EPI: 0 = fp16 store; 1 = fp16 gelu(acc+bias); 2 = fp32 gated residual.
#define KPA 40     // A stage row pitch (halves)
#define BPB 136    // B stage row pitch (halves)
#define ASTG 5120  // 128*40
#define BSTG 4352  // 32*136
#define GSM_BYTES ((3 * (ASTG + BSTG)) * 2)   // 56832

template <int EPI>
__global__ void __launch_bounds__(256) gemm_h(
    const __half* __restrict__ A, const __half* __restrict__ B, void* __restrict__ Cv,
    int Kd, int lda, int ldb, int ldc,
    const float* __restrict__ bias, const float* __restrict__ modv, int goff,
    const void* __restrict__ en, const float* __restrict__ basep)
{
    extern __shared__ __half smh[];
    const uint32_t smw = smem_u32(smh);

    const int tid = threadIdx.x;
    const int lane = tid & 31;
    const int wid = tid >> 5;
    const int wm = wid >> 2, wn = wid & 3;
    const int lq = lane >> 2, lr = lane & 3;
    const int rsel = lane & 15;            // row/k-row selector for x4 groups
    const int ksel = (lane >> 4) * 8;      // second-half selector

    const int row0 = blockIdx.y * 128, col0 = blockIdx.x * 128;

    float acc[4][4][4];
    #pragma unroll
    for (int i = 0; i < 4; i++)
        #pragma unroll
        for (int j = 0; j < 4; j++)
            #pragma unroll
            for (int e = 0; e < 4; e++) acc[i][j][e] = 0.f;

    const int nk = Kd / 32;

    auto load_stage = [&](int ks) {
        const int k0 = ks * 32;
        const int s = ks % 3;
        uint32_t abase = smw + (uint32_t)s * ASTG * 2;
        #pragma unroll
        for (int j = 0; j < 2; j++) {
            int idx = tid + 256 * j;
            int r = idx >> 2, c = idx & 3;
            CP_ASYNC16(abase + (uint32_t)(r * KPA + c * 8) * 2,
                       A + (size_t)(row0 + r) * lda + k0 + c * 8);
        }
        uint32_t bbase = smw + (uint32_t)(3 * ASTG + s * BSTG) * 2;
        #pragma unroll
        for (int j = 0; j < 2; j++) {
            int idx = tid + 256 * j;
            int r = idx >> 4, c = idx & 15;
            CP_ASYNC16(bbase + (uint32_t)(r * BPB + c * 8) * 2,
                       B + (size_t)(k0 + r) * ldb + col0 + c * 8);
        }
        CP_COMMIT();
    };

    load_stage(0);
    if (nk > 1) load_stage(1);

    for (int i = 0; i < nk; i++) {
        if (i == nk - 1) CP_WAIT0(); else CP_WAIT1();
        __syncthreads();
        if (i + 2 < nk) load_stage(i + 2);

        const int s = i % 3;
        const uint32_t abase = smw + (uint32_t)s * ASTG * 2;
        const uint32_t bbase = smw + (uint32_t)(3 * ASTG + s * BSTG) * 2;

        #pragma unroll
        for (int kt = 0; kt < 2; kt++) {
            uint32_t af[4][4];
            #pragma unroll
            for (int mi = 0; mi < 4; mi++) {
                int rm = wm * 64 + mi * 16;
                LDSM_X4(af[mi][0], af[mi][1], af[mi][2], af[mi][3],
                        abase + (uint32_t)((rm + rsel) * KPA + kt * 16 + ksel) * 2);
            }
            #pragma unroll
            for (int njp = 0; njp < 2; njp++) {
                uint32_t b0, b1, b2, b3;
                int n0 = wn * 32 + njp * 16;
                LDSM_X4_T(b0, b1, b2, b3,
                          bbase + (uint32_t)((kt * 16 + rsel) * BPB + n0 + ksel) * 2);
                #pragma unroll
                for (int mi = 0; mi < 4; mi++) {
                    mma_f16(acc[mi][2 * njp],     af[mi][0], af[mi][1], af[mi][2], af[mi][3], b0, b1);
                    mma_f16(acc[mi][2 * njp + 1], af[mi][0], af[mi][1], af[mi][2], af[mi][3], b2, b3);
                }
            }
        }
        __syncthreads();
    }

    // ---- epilogue ----
    #pragma unroll
    for (int mi = 0; mi < 4; mi++) {
        int rg = row0 + wm * 64 + mi * 16 + lq;
        float g0 = 0.f, g1 = 0.f;
        if (EPI == 2) {
            int e0 = g_enIsByte ? (int)((const unsigned char*)en)[rg] : ((const int*)en)[rg];
            int e1 = g_enIsByte ? (int)((const unsigned char*)en)[rg + 8] : ((const int*)en)[rg + 8];
            g0 = e0 ? 1.f : 0.f;
            g1 = e1 ? 1.f : 0.f;
        }
        #pragma unroll
        for (int nj = 0; nj < 4; nj++) {
            int cg = col0 + wn * 32 + nj * 8 + lr * 2;
            float v0 = acc[mi][nj][0], v1 = acc[mi][nj][1];
            float v2 = acc[mi][nj][2], v3 = acc[mi][nj][3];
            if (EPI == 0) {
                __half* C = (__half*)Cv;
                *(half2*)(C + (size_t)rg * ldc + cg) = __floats2half2_rn(v0, v1);
                *(half2*)(C + (size_t)(rg + 8) * ldc + cg) = __floats2half2_rn(v2, v3);
            } else if (EPI == 1) {
                float b0 = bias[cg], b1v = bias[cg + 1];
                __half* C = (__half*)Cv;
                *(half2*)(C + (size_t)rg * ldc + cg) =
                    __floats2half2_rn(gelu_f(v0 + b0), gelu_f(v1 + b1v));
                *(half2*)(C + (size_t)(rg + 8) * ldc + cg) =
                    __floats2half2_rn(gelu_f(v2 + b0), gelu_f(v3 + b1v));
            } else {
                float b0 = bias ? bias[cg] : 0.f, b1v = bias ? bias[cg + 1] : 0.f;
                int bb0 = rg >> 10, bb1 = (rg + 8) >> 10;
                float m00 = modv[bb0 * SIXD + goff + cg];
                float m01 = modv[bb0 * SIXD + goff + cg + 1];
                float m10 = modv[bb1 * SIXD + goff + cg];
                float m11 = modv[bb1 * SIXD + goff + cg + 1];
                float* C = (float*)Cv;
                *(float2*)(C + (size_t)rg * ldc + cg) = make_float2(
                    basep[(size_t)rg * DD + cg] + g0 * m00 * (v0 + b0),
                    basep[(size_t)rg * DD + cg + 1] + g0 * m01 * (v1 + b1v));
                *(float2*)(C + (size_t)(rg + 8) * ldc + cg) = make_float2(
                    basep[(size_t)(rg + 8) * DD + cg] + g1 * m10 * (v2 + b0),
                    basep[(size_t)(rg + 8) * DD + cg + 1] + g1 * m11 * (v3 + b1v));
            }
        }
    }
}

// ================= flash attention (fp16 mma) =================
// Grid (S/128, B*H), 256 thr, warp w owns q-rows w*16..+15.
// SMEM halves: Qs[128][72] @0, Ks @9216, Vs @18432, Ps[128][136] @27648,
// grpq int @half 45056, grpk @ +128 ints. Bytes = 91136.
#define FQP 72
#define FPP 136
#define FKO 9216
#define FVO 18432
#define FPO 27648
#define FL_BYTES (45056 * 2 + 1024)

__global__ void __launch_bounds__(256) flash_h(
    const __half* __restrict__ q, const __half* __restrict__ kv,
    const int* __restrict__ grp, __half* __restrict__ attn)
{
    extern __shared__ __half smh[];
    const uint32_t smw = smem_u32(smh);
    int* grpq = (int*)(smh + 45056);
    int* grpk = grpq + 128;

    const int tid = threadIdx.x;
    const int lane = tid & 31;
    const int wid = tid >> 5;
    const int wr0 = wid * 16;
    const int lq = lane >> 2, lr = lane & 3;
    const int rsel = lane & 15;
    const int ksel = (lane >> 4) * 8;
    const int nsel = (lane & 7) + (lane >> 4) * 8;  // for K B-frags (non-trans pair style)
    const int kse2 = ((lane >> 3) & 1) * 8;

    const int qb = blockIdx.x;
    const int b = blockIdx.y >> 4;
    const int h = blockIdx.y & 15;

    #pragma unroll
    for (int j = 0; j < 4; j++) {
        int idx = tid + 256 * j;
        int r = idx >> 3, c = idx & 7;
        CP_ASYNC16(smw + (uint32_t)(r * FQP + c * 8) * 2,
                   q + (size_t)(b * SS + qb * 128 + r) * DD + h * HD + c * 8);
    }
    CP_COMMIT();
    if (tid < 128) grpq[tid] = grp[b * 1024 + qb * 128 + tid];

    float m0 = -3.0e38f, m1 = -3.0e38f, l0 = 0.f, l1 = 0.f;
    float oacc[8][4];
    #pragma unroll
    for (int j = 0; j < 8; j++)
        #pragma unroll
        for (int e = 0; e < 4; e++) oacc[j][e] = 0.f;

    for (int kc = 0; kc < 8; kc++) {
        #pragma unroll
        for (int j = 0; j < 4; j++) {
            int idx = tid + 256 * j;
            int r = idx >> 3, c = idx & 7;
            const __half* src = kv + (size_t)(b * 1024 + kc * 128 + r) * (2 * DD) + h * HD + c * 8;
            CP_ASYNC16(smw + (uint32_t)(FKO + r * FQP + c * 8) * 2, src);
            CP_ASYNC16(smw + (uint32_t)(FVO + r * FQP + c * 8) * 2, src + DD);
        }
        CP_COMMIT();
        if (tid < 128) grpk[tid] = grp[b * 1024 + kc * 128 + tid];
        CP_WAIT0();
        __syncthreads();

        // ---- S = Q @ K^T ----
        float sacc[16][4];
        #pragma unroll
        for (int nj = 0; nj < 16; nj++)
            #pragma unroll
            for (int e = 0; e < 4; e++) sacc[nj][e] = 0.f;

        #pragma unroll
        for (int kt = 0; kt < 4; kt++) {
            uint32_t a0, a1, a2, a3;
            LDSM_X4(a0, a1, a2, a3,
                    smw + (uint32_t)((wr0 + rsel) * FQP + kt * 16 + ksel) * 2);
            #pragma unroll
            for (int njp = 0; njp < 8; njp++) {
                uint32_t b0, b1, b2, b3;
                LDSM_X4(b0, b1, b2, b3,
                        smw + (uint32_t)(FKO + (njp * 16 + nsel) * FQP + kt * 16 + kse2) * 2);
                mma_f16(sacc[2 * njp],     a0, a1, a2, a3, b0, b1);
                mma_f16(sacc[2 * njp + 1], a0, a1, a2, a3, b2, b3);
            }
        }

        // ---- scale + mask + running softmax ----
        int gq0 = grpq[wr0 + lq], gq1 = grpq[wr0 + lq + 8];
        float rm0 = -3.0e38f, rm1 = -3.0e38f;
        #pragma unroll
        for (int nj = 0; nj < 16; nj++) {
            int c0i = nj * 8 + 2 * lr;
            int gk0 = grpk[c0i], gk1 = grpk[c0i + 1];
            float s0 = (gk0 != gq0) ? sacc[nj][0] * INV_SQRT_HD : -1.0e9f;
            float s1 = (gk1 != gq0) ? sacc[nj][1] * INV_SQRT_HD : -1.0e9f;
            float s2 = (gk0 != gq1) ? sacc[nj][2] * INV_SQRT_HD : -1.0e9f;
            float s3 = (gk1 != gq1) ? sacc[nj][3] * INV_SQRT_HD : -1.0e9f;
            sacc[nj][0] = s0; sacc[nj][1] = s1; sacc[nj][2] = s2; sacc[nj][3] = s3;
            rm0 = fmaxf(rm0, fmaxf(s0, s1));
            rm1 = fmaxf(rm1, fmaxf(s2, s3));
        }
        rm0 = fmaxf(rm0, __shfl_xor_sync(0xffffffffu, rm0, 1));
        rm0 = fmaxf(rm0, __shfl_xor_sync(0xffffffffu, rm0, 2));
        rm1 = fmaxf(rm1, __shfl_xor_sync(0xffffffffu, rm1, 1));
        rm1 = fmaxf(rm1, __shfl_xor_sync(0xffffffffu, rm1, 2));
        float mn0 = fmaxf(m0, rm0), mn1 = fmaxf(m1, rm1);
        float al0 = __expf(m0 - mn0), al1 = __expf(m1 - mn1);

        __half* Ps = smh + FPO;
        float ps0 = 0.f, ps1 = 0.f;
        #pragma unroll
        for (int nj = 0; nj < 16; nj++) {
            float e0 = __expf(sacc[nj][0] - mn0);
            float e1 = __expf(sacc[nj][1] - mn0);
            float e2 = __expf(sacc[nj][2] - mn1);
            float e3 = __expf(sacc[nj][3] - mn1);
            ps0 += e0 + e1; ps1 += e2 + e3;
            int c0i = nj * 8 + 2 * lr;
            *(half2*)(Ps + (wr0 + lq) * FPP + c0i) = __floats2half2_rn(e0, e1);
            *(half2*)(Ps + (wr0 + lq + 8) * FPP + c0i) = __floats2half2_rn(e2, e3);
        }
        ps0 += __shfl_xor_sync(0xffffffffu, ps0, 1);
        ps0 += __shfl_xor_sync(0xffffffffu, ps0, 2);
        ps1 += __shfl_xor_sync(0xffffffffu, ps1, 1);
        ps1 += __shfl_xor_sync(0xffffffffu, ps1, 2);
        l0 = l0 * al0 + ps0;
        l1 = l1 * al1 + ps1;
        m0 = mn0; m1 = mn1;

        #pragma unroll
        for (int nj = 0; nj < 8; nj++) {
            oacc[nj][0] *= al0; oacc[nj][1] *= al0;
            oacc[nj][2] *= al1; oacc[nj][3] *= al1;
        }
        __syncwarp();

        // ---- O += P @ V ----
        #pragma unroll
        for (int kt = 0; kt < 8; kt++) {
            uint32_t a0, a1, a2, a3;
            LDSM_X4(a0, a1, a2, a3,
                    smw + (uint32_t)(FPO + (wr0 + rsel) * FPP + kt * 16 + ksel) * 2);
            #pragma unroll
            for (int njp = 0; njp < 4; njp++) {
                uint32_t b0, b1, b2, b3;
                LDSM_X4_T(b0, b1, b2, b3,
                          smw + (uint32_t)(FVO + (kt * 16 + rsel) * FQP + njp * 16 + ksel) * 2);
                mma_f16(oacc[2 * njp],     a0, a1, a2, a3, b0, b1);
                mma_f16(oacc[2 * njp + 1], a0, a1, a2, a3, b2, b3);
            }
        }
        __syncthreads();
    }

    float il0 = 1.0f / l0, il1 = 1.0f / l1;
    int r0 = b * 1024 + qb * 128 + wr0 + lq;
    #pragma unroll
    for (int nj = 0; nj < 8; nj++) {
        int cg = h * HD + nj * 8 + 2 * lr;
        *(half2*)(attn + (size_t)r0 * DD + cg) =
            __floats2half2_rn(oacc[nj][0] * il0, oacc[nj][1] * il0);
        *(half2*)(attn + (size_t)(r0 + 8) * DD + cg) =
            __floats2half2_rn(oacc[nj][2] * il1, oacc[nj][3] * il1);
    }
}

// ================= small kernels =================
__device__ __forceinline__ float warpSum(float v) {
    #pragma unroll
    for (int o = 16; o; o >>= 1) v += __shfl_xor_sync(0xffffffffu, v, o);
    return v;
}
__device__ __forceinline__ float blockSum(float v, float* sh) {
    int tid = threadIdx.x;
    v = warpSum(v);
    if ((tid & 31) == 0) sh[tid >> 5] = v;
    __syncthreads();
    if (tid == 0) {
        float t = 0.f;
        #pragma unroll
        for (int i = 0; i < 8; i++) t += sh[i];
        sh[0] = t;
    }
    __syncthreads();
    float r = sh[0];
    __syncthreads();
    return r;
}

__global__ void __launch_bounds__(1024) detect_en_k(const int* __restrict__ en32) {
    __shared__ int sh[32];
    int v = en32[threadIdx.x];
    int f = (v & ~1) ? 1 : 0;
    #pragma unroll
    for (int o = 16; o; o >>= 1) f |= __shfl_xor_sync(0xffffffffu, f, o);
    if ((threadIdx.x & 31) == 0) sh[threadIdx.x >> 5] = f;
    __syncthreads();
    if (threadIdx.x == 0) {
        int t = 0;
        #pragma unroll
        for (int i = 0; i < 32; i++) t |= sh[i];
        g_enIsByte = t;
    }
}

__global__ void __launch_bounds__(256) wcvt_k(const float* __restrict__ src,
                                              __half* __restrict__ dst) {
    int i = blockIdx.x * 256 + threadIdx.x;
    float4 v = *(const float4*)(src + (size_t)i * 4);
    half2* d = (half2*)(dst + (size_t)i * 4);
    d[0] = __floats2half2_rn(v.x, v.y);
    d[1] = __floats2half2_rn(v.z, v.w);
}

__global__ void __launch_bounds__(256) mod_k(const float* __restrict__ t_cond,
                                             const float* __restrict__ adaW,
                                             const float* __restrict__ adab,
                                             float* __restrict__ mod) {
    __shared__ float tc[1024];
    int b  = blockIdx.x / 24;
    int cg = blockIdx.x % 24;
    for (int i = threadIdx.x; i < 1024; i += 256) tc[i] = t_cond[b * 1024 + i];
    __syncthreads();
    int col = cg * 256 + threadIdx.x;
    float acc = adab[col];
    #pragma unroll 4
    for (int i = 0; i < 1024; i++) acc = fmaf(tc[i], adaW[(size_t)i * SIXD + col], acc);
    mod[b * SIXD + col] = acc;
}

// LN -> fp16 out (+ optional adaLN)
__global__ void __launch_bounds__(256) ln_mod_k(const float* __restrict__ x,
                                                const float* __restrict__ w,
                                                const float* __restrict__ mod,
                                                int shOff, int scOff, int useMod,
                                                __half* __restrict__ out) {
    __shared__ float sh[8];
    int row = blockIdx.x;
    int b = row >> 10;
    const float* xr = x + (size_t)row * DD;
    int tid = threadIdx.x;
    float v[4];
    float s = 0.f, s2 = 0.f;
    #pragma unroll
    for (int j = 0; j < 4; j++) {
        v[j] = xr[tid + j * 256];
        s += v[j];
        s2 = fmaf(v[j], v[j], s2);
    }
    s  = blockSum(s, sh);
    s2 = blockSum(s2, sh);
    float mu = s * (1.0f / DD);
    float var = s2 * (1.0f / DD) - mu * mu;
    float rs = rsqrtf(var + 1e-5f);
    __half* orow = out + (size_t)row * DD;
    #pragma unroll
    for (int j = 0; j < 4; j++) {
        int d = tid + j * 256;
        float y = (v[j] - mu) * rs * w[d];
        if (useMod) y = y * (1.0f + mod[b * SIXD + scOff + d]) + mod[b * SIXD + shOff + d];
        orow[d] = __float2half_rn(y);
    }
}

__global__ void __launch_bounds__(256) rope_h_k(__half* __restrict__ x,
                                                const float* __restrict__ cosp,
                                                const float* __restrict__ sinp,
                                                int rowStride) {
    int idx = blockIdx.x * 256 + threadIdx.x;
    int d = idx & 31;
    int h = (idx >> 5) & 15;
    int rs = idx >> 9;
    int s = rs & 1023;
    __half* p = x + (size_t)rs * rowStride + h * HD + d;
    float x1 = __half2float(p[0]), x2 = __half2float(p[32]);
    float c1 = cosp[s * HD + d],      sn1 = sinp[s * HD + d];
    float c2 = cosp[s * HD + d + 32], sn2 = sinp[s * HD + d + 32];
    p[0]  = __float2half_rn(x1 * c1 - x2 * sn1);
    p[32] = __float2half_rn(x2 * c2 + x1 * sn2);
}

// ================= host =================
extern "C" void kernel_launch(void* const* d_in, const int* in_sizes, int n_in,
                              void* d_out, int out_size) {
    const float* q_x    = (const float*)d_in[0];
    const float* kv_x   = (const float*)d_in[1];
    const float* t_cond = (const float*)d_in[2];
    const float* cos_q  = (const float*)d_in[3];
    const float* sin_q  = (const float*)d_in[4];
    const float* cos_k  = (const float*)d_in[5];
    const float* sin_k  = (const float*)d_in[6];
    const int*   grp    = (const int*)d_in[7];
    const void*  en     = d_in[8];
    const float* qn_w   = (const float*)d_in[9];
    const float* kvn_w  = (const float*)d_in[10];
    const float* n2_w   = (const float*)d_in[11];
    const float* Wq     = (const float*)d_in[12];
    const float* Wkv    = (const float*)d_in[13];
    const float* Wo     = (const float*)d_in[14];
    const float* W1     = (const float*)d_in[15];
    const float* b1     = (const float*)d_in[16];
    const float* W2     = (const float*)d_in[17];
    const float* b2     = (const float*)d_in[18];
    const float* adaW   = (const float*)d_in[19];
    const float* adab   = (const float*)d_in[20];
    float* out = (float*)d_out;

    float *mod, *x;
    __half *qn_h, *kvn_h, *q_h, *kv_h, *attn_h, *hh, *h1_h;
    __half *wq_h, *wkv_h, *wo_h, *w1_h, *w2_h;
    cudaGetSymbolAddress((void**)&mod,    g_mod);
    cudaGetSymbolAddress((void**)&x,      g_x);
    cudaGetSymbolAddress((void**)&qn_h,   g_qn_h);
    cudaGetSymbolAddress((void**)&kvn_h,  g_kvn_h);
    cudaGetSymbolAddress((void**)&q_h,    g_q_h);
    cudaGetSymbolAddress((void**)&kv_h,   g_kv_h);
    cudaGetSymbolAddress((void**)&attn_h, g_attn_h);
    cudaGetSymbolAddress((void**)&hh,     g_hh);
    cudaGetSymbolAddress((void**)&h1_h,   g_h1_h);
    cudaGetSymbolAddress((void**)&wq_h,   g_wq_h);
    cudaGetSymbolAddress((void**)&wkv_h,  g_wkv_h);
    cudaGetSymbolAddress((void**)&wo_h,   g_wo_h);
    cudaGetSymbolAddress((void**)&w1_h,   g_w1_h);
    cudaGetSymbolAddress((void**)&w2_h,   g_w2_h);

    cudaFuncSetAttribute(gemm_h<0>, cudaFuncAttributeMaxDynamicSharedMemorySize, GSM_BYTES);
    cudaFuncSetAttribute(gemm_h<1>, cudaFuncAttributeMaxDynamicSharedMemorySize, GSM_BYTES);
    cudaFuncSetAttribute(gemm_h<2>, cudaFuncAttributeMaxDynamicSharedMemorySize, GSM_BYTES);
    cudaFuncSetAttribute(flash_h, cudaFuncAttributeMaxDynamicSharedMemorySize, FL_BYTES);

    detect_en_k<<<1, 1024>>>((const int*)en);
    mod_k<<<BB * (SIXD / 256), 256>>>(t_cond, adaW, adab, mod);

    // weight conversion fp32 -> fp16 (layouts preserved)
    wcvt_k<<<DD * DD / 1024, 256>>>(Wq, wq_h);
    wcvt_k<<<DD * 2 * DD / 1024, 256>>>(Wkv, wkv_h);
    wcvt_k<<<DD * DD / 1024, 256>>>(Wo, wo_h);
    wcvt_k<<<DD * MRD / 1024, 256>>>(W1, w1_h);
    wcvt_k<<<MRD * DD / 1024, 256>>>(W2, w2_h);

    ln_mod_k<<<NBS, 256>>>(q_x, qn_w, mod, 0, DD, 1, qn_h);
    ln_mod_k<<<NBS, 256>>>(kv_x, kvn_w, mod, 0, 0, 0, kvn_h);

    gemm_h<0><<<dim3(8, 32), 256, GSM_BYTES>>>(
        qn_h, wq_h, q_h, DD, DD, DD, DD, nullptr, nullptr, 0, nullptr, nullptr);
    gemm_h<0><<<dim3(16, 32), 256, GSM_BYTES>>>(
        kvn_h, wkv_h, kv_h, DD, DD, 2 * DD, 2 * DD, nullptr, nullptr, 0, nullptr, nullptr);

    rope_h_k<<<(NBS * HH * 32) / 256, 256>>>(q_h, cos_q, sin_q, DD);
    rope_h_k<<<(NBS * HH * 32) / 256, 256>>>(kv_h, cos_k, sin_k, 2 * DD);

    flash_h<<<dim3(SS / 128, BB * HH), 256, FL_BYTES>>>(q_h, kv_h, grp, attn_h);

    gemm_h<2><<<dim3(8, 32), 256, GSM_BYTES>>>(
        attn_h, wo_h, x, DD, DD, DD, DD, nullptr, mod, 2 * DD, en, q_x);

    ln_mod_k<<<NBS, 256>>>(x, n2_w, mod, 3 * DD, 4 * DD, 1, hh);

    gemm_h<1><<<dim3(32, 32), 256, GSM_BYTES>>>(
        hh, w1_h, h1_h, DD, DD, MRD, MRD, b1, nullptr, 0, nullptr, nullptr);
    gemm_h<2><<<dim3(8, 32), 256, GSM_BYTES>>>(
        h1_h, w2_h, out, MRD, MRD, DD, DD, b2, mod, 5 * DD, en, x);
}

// round 8
// speedup vs baseline: 5.9561x; 1.1165x over previous
#include <cuda_runtime.h>
#include <cuda_fp16.h>
#include <cstdint>

// Problem constants
#define BB 4
#define SS 1024
#define KK 1024
#define DD 1024
#define HH 16
#define HD 64
#define MRD 4096
#define SIXD 6144
#define NBS 4096
#define INV_SQRT_HD 0.125f
#define GELU_C 0.7978845608028654f

// ---------------- scratch ----------------
__device__ __align__(16) float  g_mod[BB * SIXD];
__device__ __align__(16) float  g_x[NBS * DD];
__device__ __align__(16) __half g_qn_h[NBS * DD];
__device__ __align__(16) __half g_kvn_h[NBS * DD];
__device__ __align__(16) __half g_q_h[NBS * DD];
__device__ __align__(16) __half g_kv_h[NBS * 2 * DD];
__device__ __align__(16) __half g_attn_h[NBS * DD];
__device__ __align__(16) __half g_hh[NBS * DD];
__device__ __align__(16) __half g_h1_h[(size_t)NBS * MRD];
__device__ __align__(16) __half g_wq_h[DD * DD];
__device__ __align__(16) __half g_wkv_h[DD * 2 * DD];
__device__ __align__(16) __half g_wo_h[DD * DD];
__device__ __align__(16) __half g_w1_h[DD * MRD];
__device__ __align__(16) __half g_w2_h[MRD * DD];
__device__ int    g_enIsByte;

// ================= PTX helpers =================
__device__ __forceinline__ uint32_t smem_u32(const void* p) {
    uint32_t a;
    asm("{ .reg .u64 t; cvta.to.shared.u64 t, %1; cvt.u32.u64 %0, t; }" : "=r"(a) : "l"(p));
    return a;
}
#define CP_ASYNC16(sa, ga) \
    asm volatile("cp.async.ca.shared.global [%0], [%1], 16;" :: "r"(sa), "l"(ga) : "memory")
#define CP_COMMIT() asm volatile("cp.async.commit_group;" ::: "memory")
#define CP_WAIT0()  asm volatile("cp.async.wait_group 0;" ::: "memory")
#define CP_WAIT1()  asm volatile("cp.async.wait_group 1;" ::: "memory")

#define LDSM_X4(d0, d1, d2, d3, addr)                                          \
    asm volatile("ldmatrix.sync.aligned.m8n8.x4.shared.b16 {%0,%1,%2,%3}, [%4];" \
        : "=r"(d0), "=r"(d1), "=r"(d2), "=r"(d3) : "r"(addr))
#define LDSM_X4_T(d0, d1, d2, d3, addr)                                        \
    asm volatile("ldmatrix.sync.aligned.m8n8.x4.trans.shared.b16 {%0,%1,%2,%3}, [%4];" \
        : "=r"(d0), "=r"(d1), "=r"(d2), "=r"(d3) : "r"(addr))

__device__ __forceinline__ void mma_f16(float* c, uint32_t a0, uint32_t a1,
                                        uint32_t a2, uint32_t a3,
                                        uint32_t b0, uint32_t b1) {
    asm volatile(
        "mma.sync.aligned.m16n8k16.row.col.f32.f16.f16.f32 "
        "{%0,%1,%2,%3}, {%4,%5,%6,%7}, {%8,%9}, {%0,%1,%2,%3};"
        : "+f"(c[0]), "+f"(c[1]), "+f"(c[2]), "+f"(c[3])
        : "r"(a0), "r"(a1), "r"(a2), "r"(a3), "r"(b0), "r"(b1));
}
__device__ __forceinline__ float gelu_f(float v) {
    float u = GELU_C * (v + 0.044715f * v * v * v);
    u = fminf(fmaxf(u, -15.f), 15.f);
    float t = __expf(2.0f * u);
    return 0.5f * v * (1.0f + (t - 1.0f) / (t + 1.0f));
}

// ================= fp16 mma GEMM: BK=64, 2-stage, occ-2 =================
// C[M,N] = A[M,K] @ B[K,N]; fp16 in, fp32 acc. CTA 128x128, 8 warps (2x4).
// EPI: 0 = fp16 store; 1 = fp16 gelu(acc+bias); 2 = fp32 gated residual.
#define KPA 72      // A stage row pitch (halves): 64 + 8 pad
#define BPB 136     // B stage row pitch (halves): 128 + 8 pad
#define ASTG (128 * KPA)   // 9216 halves
#define BSTG (64 * BPB)    // 8704 halves
#define GSM_BYTES (2 * (ASTG + BSTG) * 2)   // 71680 bytes

template <int EPI>
__global__ void __launch_bounds__(256, 2) gemm_h(
    const __half* __restrict__ A, const __half* __restrict__ B, void* __restrict__ Cv,
    int Kd, int lda, int ldb, int ldc,
    const float* __restrict__ bias, const float* __restrict__ modv, int goff,
    const void* __restrict__ en, const float* __restrict__ basep)
{
    extern __shared__ __half smh[];
    const uint32_t smw = smem_u32(smh);

    const int tid = threadIdx.x;
    const int lane = tid & 31;
    const int wid = tid >> 5;
    const int wm = wid >> 2, wn = wid & 3;
    const int lq = lane >> 2, lr = lane & 3;
    const int rsel = lane & 15;
    const int ksel = (lane >> 4) * 8;

    const int row0 = blockIdx.y * 128, col0 = blockIdx.x * 128;

    float acc[4][4][4];
    #pragma unroll
    for (int i = 0; i < 4; i++)
        #pragma unroll
        for (int j = 0; j < 4; j++)
            #pragma unroll
            for (int e = 0; e < 4; e++) acc[i][j][e] = 0.f;

    const int nk = Kd / 64;

    auto load_stage = [&](int ks) {
        const int k0 = ks * 64;
        const int s = ks & 1;
        uint32_t abase = smw + (uint32_t)s * ASTG * 2;
        #pragma unroll
        for (int j = 0; j < 4; j++) {
            int idx = tid + 256 * j;
            int r = idx >> 3, c = idx & 7;
            CP_ASYNC16(abase + (uint32_t)(r * KPA + c * 8) * 2,
                       A + (size_t)(row0 + r) * lda + k0 + c * 8);
        }
        uint32_t bbase = smw + (uint32_t)(2 * ASTG + s * BSTG) * 2;
        #pragma unroll
        for (int j = 0; j < 4; j++) {
            int idx = tid + 256 * j;
            int r = idx >> 4, c = idx & 15;
            CP_ASYNC16(bbase + (uint32_t)(r * BPB + c * 8) * 2,
                       B + (size_t)(k0 + r) * ldb + col0 + c * 8);
        }
        CP_COMMIT();
    };

    load_stage(0);
    if (nk > 1) load_stage(1);

    for (int i = 0; i < nk; i++) {
        if (i == nk - 1) CP_WAIT0(); else CP_WAIT1();
        __syncthreads();

        const int s = i & 1;
        const uint32_t abase = smw + (uint32_t)s * ASTG * 2;
        const uint32_t bbase = smw + (uint32_t)(2 * ASTG + s * BSTG) * 2;

        #pragma unroll
        for (int kt = 0; kt < 4; kt++) {
            uint32_t af[4][4];
            #pragma unroll
            for (int mi = 0; mi < 4; mi++) {
                int rm = wm * 64 + mi * 16;
                LDSM_X4(af[mi][0], af[mi][1], af[mi][2], af[mi][3],
                        abase + (uint32_t)((rm + rsel) * KPA + kt * 16 + ksel) * 2);
            }
            #pragma unroll
            for (int njp = 0; njp < 2; njp++) {
                uint32_t b0, b1, b2, b3;
                int n0 = wn * 32 + njp * 16;
                LDSM_X4_T(b0, b1, b2, b3,
                          bbase + (uint32_t)((kt * 16 + rsel) * BPB + n0 + ksel) * 2);
                #pragma unroll
                for (int mi = 0; mi < 4; mi++) {
                    mma_f16(acc[mi][2 * njp],     af[mi][0], af[mi][1], af[mi][2], af[mi][3], b0, b1);
                    mma_f16(acc[mi][2 * njp + 1], af[mi][0], af[mi][1], af[mi][2], af[mi][3], b2, b3);
                }
            }
        }
        __syncthreads();
        if (i + 2 < nk) load_stage(i + 2);
    }

    // ---- epilogue ----
    #pragma unroll
    for (int mi = 0; mi < 4; mi++) {
        int rg = row0 + wm * 64 + mi * 16 + lq;
        float g0 = 0.f, g1 = 0.f;
        if (EPI == 2) {
            int e0 = g_enIsByte ? (int)((const unsigned char*)en)[rg] : ((const int*)en)[rg];
            int e1 = g_enIsByte ? (int)((const unsigned char*)en)[rg + 8] : ((const int*)en)[rg + 8];
            g0 = e0 ? 1.f : 0.f;
            g1 = e1 ? 1.f : 0.f;
        }
        #pragma unroll
        for (int nj = 0; nj < 4; nj++) {
            int cg = col0 + wn * 32 + nj * 8 + lr * 2;
            float v0 = acc[mi][nj][0], v1 = acc[mi][nj][1];
            float v2 = acc[mi][nj][2], v3 = acc[mi][nj][3];
            if (EPI == 0) {
                __half* C = (__half*)Cv;
                *(half2*)(C + (size_t)rg * ldc + cg) = __floats2half2_rn(v0, v1);
                *(half2*)(C + (size_t)(rg + 8) * ldc + cg) = __floats2half2_rn(v2, v3);
            } else if (EPI == 1) {
                float b0 = bias[cg], b1v = bias[cg + 1];
                __half* C = (__half*)Cv;
                *(half2*)(C + (size_t)rg * ldc + cg) =
                    __floats2half2_rn(gelu_f(v0 + b0), gelu_f(v1 + b1v));
                *(half2*)(C + (size_t)(rg + 8) * ldc + cg) =
                    __floats2half2_rn(gelu_f(v2 + b0), gelu_f(v3 + b1v));
            } else {
                float b0 = bias ? bias[cg] : 0.f, b1v = bias ? bias[cg + 1] : 0.f;
                int bb0 = rg >> 10, bb1 = (rg + 8) >> 10;
                float m00 = modv[bb0 * SIXD + goff + cg];
                float m01 = modv[bb0 * SIXD + goff + cg + 1];
                float m10 = modv[bb1 * SIXD + goff + cg];
                float m11 = modv[bb1 * SIXD + goff + cg + 1];
                float* C = (float*)Cv;
                *(float2*)(C + (size_t)rg * ldc + cg) = make_float2(
                    basep[(size_t)rg * DD + cg] + g0 * m00 * (v0 + b0),
                    basep[(size_t)rg * DD + cg + 1] + g0 * m01 * (v1 + b1v));
                *(float2*)(C + (size_t)(rg + 8) * ldc + cg) = make_float2(
                    basep[(size_t)(rg + 8) * DD + cg] + g1 * m10 * (v2 + b0),
                    basep[(size_t)(rg + 8) * DD + cg + 1] + g1 * m11 * (v3 + b1v));
            }
        }
    }
}

// ================= flash attention (fp16 mma) — unchanged from R7 =================
#define FQP 72
#define FPP 136
#define FKO 9216
#define FVO 18432
#define FPO 27648
#define FL_BYTES (45056 * 2 + 1024)

__global__ void __launch_bounds__(256) flash_h(
    const __half* __restrict__ q, const __half* __restrict__ kv,
    const int* __restrict__ grp, __half* __restrict__ attn)
{
    extern __shared__ __half smh[];
    const uint32_t smw = smem_u32(smh);
    int* grpq = (int*)(smh + 45056);
    int* grpk = grpq + 128;

    const int tid = threadIdx.x;
    const int lane = tid & 31;
    const int wid = tid >> 5;
    const int wr0 = wid * 16;
    const int lq = lane >> 2, lr = lane & 3;
    const int rsel = lane & 15;
    const int ksel = (lane >> 4) * 8;
    const int nsel = (lane & 7) + (lane >> 4) * 8;
    const int kse2 = ((lane >> 3) & 1) * 8;

    const int qb = blockIdx.x;
    const int b = blockIdx.y >> 4;
    const int h = blockIdx.y & 15;

    #pragma unroll
    for (int j = 0; j < 4; j++) {
        int idx = tid + 256 * j;
        int r = idx >> 3, c = idx & 7;
        CP_ASYNC16(smw + (uint32_t)(r * FQP + c * 8) * 2,
                   q + (size_t)(b * SS + qb * 128 + r) * DD + h * HD + c * 8);
    }
    CP_COMMIT();
    if (tid < 128) grpq[tid] = grp[b * 1024 + qb * 128 + tid];

    float m0 = -3.0e38f, m1 = -3.0e38f, l0 = 0.f, l1 = 0.f;
    float oacc[8][4];
    #pragma unroll
    for (int j = 0; j < 8; j++)
        #pragma unroll
        for (int e = 0; e < 4; e++) oacc[j][e] = 0.f;

    for (int kc = 0; kc < 8; kc++) {
        #pragma unroll
        for (int j = 0; j < 4; j++) {
            int idx = tid + 256 * j;
            int r = idx >> 3, c = idx & 7;
            const __half* src = kv + (size_t)(b * 1024 + kc * 128 + r) * (2 * DD) + h * HD + c * 8;
            CP_ASYNC16(smw + (uint32_t)(FKO + r * FQP + c * 8) * 2, src);
            CP_ASYNC16(smw + (uint32_t)(FVO + r * FQP + c * 8) * 2, src + DD);
        }
        CP_COMMIT();
        if (tid < 128) grpk[tid] = grp[b * 1024 + kc * 128 + tid];
        CP_WAIT0();
        __syncthreads();

        float sacc[16][4];
        #pragma unroll
        for (int nj = 0; nj < 16; nj++)
            #pragma unroll
            for (int e = 0; e < 4; e++) sacc[nj][e] = 0.f;

        #pragma unroll
        for (int kt = 0; kt < 4; kt++) {
            uint32_t a0, a1, a2, a3;
            LDSM_X4(a0, a1, a2, a3,
                    smw + (uint32_t)((wr0 + rsel) * FQP + kt * 16 + ksel) * 2);
            #pragma unroll
            for (int njp = 0; njp < 8; njp++) {
                uint32_t b0, b1, b2, b3;
                LDSM_X4(b0, b1, b2, b3,
                        smw + (uint32_t)(FKO + (njp * 16 + nsel) * FQP + kt * 16 + kse2) * 2);
                mma_f16(sacc[2 * njp],     a0, a1, a2, a3, b0, b1);
                mma_f16(sacc[2 * njp + 1], a0, a1, a2, a3, b2, b3);
            }
        }

        int gq0 = grpq[wr0 + lq], gq1 = grpq[wr0 + lq + 8];
        float rm0 = -3.0e38f, rm1 = -3.0e38f;
        #pragma unroll
        for (int nj = 0; nj < 16; nj++) {
            int c0i = nj * 8 + 2 * lr;
            int gk0 = grpk[c0i], gk1 = grpk[c0i + 1];
            float s0 = (gk0 != gq0) ? sacc[nj][0] * INV_SQRT_HD : -1.0e9f;
            float s1 = (gk1 != gq0) ? sacc[nj][1] * INV_SQRT_HD : -1.0e9f;
            float s2 = (gk0 != gq1) ? sacc[nj][2] * INV_SQRT_HD : -1.0e9f;
            float s3 = (gk1 != gq1) ? sacc[nj][3] * INV_SQRT_HD : -1.0e9f;
            sacc[nj][0] = s0; sacc[nj][1] = s1; sacc[nj][2] = s2; sacc[nj][3] = s3;
            rm0 = fmaxf(rm0, fmaxf(s0, s1));
            rm1 = fmaxf(rm1, fmaxf(s2, s3));
        }
        rm0 = fmaxf(rm0, __shfl_xor_sync(0xffffffffu, rm0, 1));
        rm0 = fmaxf(rm0, __shfl_xor_sync(0xffffffffu, rm0, 2));
        rm1 = fmaxf(rm1, __shfl_xor_sync(0xffffffffu, rm1, 1));
        rm1 = fmaxf(rm1, __shfl_xor_sync(0xffffffffu, rm1, 2));
        float mn0 = fmaxf(m0, rm0), mn1 = fmaxf(m1, rm1);
        float al0 = __expf(m0 - mn0), al1 = __expf(m1 - mn1);

        __half* Ps = smh + FPO;
        float ps0 = 0.f, ps1 = 0.f;
        #pragma unroll
        for (int nj = 0; nj < 16; nj++) {
            float e0 = __expf(sacc[nj][0] - mn0);
            float e1 = __expf(sacc[nj][1] - mn0);
            float e2 = __expf(sacc[nj][2] - mn1);
            float e3 = __expf(sacc[nj][3] - mn1);
            ps0 += e0 + e1; ps1 += e2 + e3;
            int c0i = nj * 8 + 2 * lr;
            *(half2*)(Ps + (wr0 + lq) * FPP + c0i) = __floats2half2_rn(e0, e1);
            *(half2*)(Ps + (wr0 + lq + 8) * FPP + c0i) = __floats2half2_rn(e2, e3);
        }
        ps0 += __shfl_xor_sync(0xffffffffu, ps0, 1);
        ps0 += __shfl_xor_sync(0xffffffffu, ps0, 2);
        ps1 += __shfl_xor_sync(0xffffffffu, ps1, 1);
        ps1 += __shfl_xor_sync(0xffffffffu, ps1, 2);
        l0 = l0 * al0 + ps0;
        l1 = l1 * al1 + ps1;
        m0 = mn0; m1 = mn1;

        #pragma unroll
        for (int nj = 0; nj < 8; nj++) {
            oacc[nj][0] *= al0; oacc[nj][1] *= al0;
            oacc[nj][2] *= al1; oacc[nj][3] *= al1;
        }
        __syncwarp();

        #pragma unroll
        for (int kt = 0; kt < 8; kt++) {
            uint32_t a0, a1, a2, a3;
            LDSM_X4(a0, a1, a2, a3,
                    smw + (uint32_t)(FPO + (wr0 + rsel) * FPP + kt * 16 + ksel) * 2);
            #pragma unroll
            for (int njp = 0; njp < 4; njp++) {
                uint32_t b0, b1, b2, b3;
                LDSM_X4_T(b0, b1, b2, b3,
                          smw + (uint32_t)(FVO + (kt * 16 + rsel) * FQP + njp * 16 + ksel) * 2);
                mma_f16(oacc[2 * njp],     a0, a1, a2, a3, b0, b1);
                mma_f16(oacc[2 * njp + 1], a0, a1, a2, a3, b2, b3);
            }
        }
        __syncthreads();
    }

    float il0 = 1.0f / l0, il1 = 1.0f / l1;
    int r0 = b * 1024 + qb * 128 + wr0 + lq;
    #pragma unroll
    for (int nj = 0; nj < 8; nj++) {
        int cg = h * HD + nj * 8 + 2 * lr;
        *(half2*)(attn + (size_t)r0 * DD + cg) =
            __floats2half2_rn(oacc[nj][0] * il0, oacc[nj][1] * il0);
        *(half2*)(attn + (size_t)(r0 + 8) * DD + cg) =
            __floats2half2_rn(oacc[nj][2] * il1, oacc[nj][3] * il1);
    }
}

// ================= small kernels =================
__global__ void __launch_bounds__(1024) detect_en_k(const int* __restrict__ en32) {
    __shared__ int sh[32];
    int v = en32[threadIdx.x];
    int f = (v & ~1) ? 1 : 0;
    #pragma unroll
    for (int o = 16; o; o >>= 1) f |= __shfl_xor_sync(0xffffffffu, f, o);
    if ((threadIdx.x & 31) == 0) sh[threadIdx.x >> 5] = f;
    __syncthreads();
    if (threadIdx.x == 0) {
        int t = 0;
        #pragma unroll
        for (int i = 0; i < 32; i++) t |= sh[i];
        g_enIsByte = t;
    }
}

// fp32 -> fp16 weight convert, 16 elems/thread
__global__ void __launch_bounds__(256) wcvt_k(const float* __restrict__ src,
                                              __half* __restrict__ dst) {
    size_t base = ((size_t)blockIdx.x * 256 + threadIdx.x) * 16;
    #pragma unroll
    for (int j = 0; j < 4; j++) {
        float4 v = *(const float4*)(src + base + 4 * j);
        half2* d = (half2*)(dst + base + 4 * j);
        d[0] = __floats2half2_rn(v.x, v.y);
        d[1] = __floats2half2_rn(v.z, v.w);
    }
}

__global__ void __launch_bounds__(256) mod_k(const float* __restrict__ t_cond,
                                             const float* __restrict__ adaW,
                                             const float* __restrict__ adab,
                                             float* __restrict__ mod) {
    __shared__ float tc[1024];
    int b  = blockIdx.x / 24;
    int cg = blockIdx.x % 24;
    for (int i = threadIdx.x; i < 1024; i += 256) tc[i] = t_cond[b * 1024 + i];
    __syncthreads();
    int col = cg * 256 + threadIdx.x;
    float acc = adab[col];
    #pragma unroll 4
    for (int i = 0; i < 1024; i++) acc = fmaf(tc[i], adaW[(size_t)i * SIXD + col], acc);
    mod[b * SIXD + col] = acc;
}

// warp-per-row LayerNorm -> fp16 (+ optional adaLN). grid = NBS/8, 256 thr.
__global__ void __launch_bounds__(256) ln_mod_k(const float* __restrict__ x,
                                                const float* __restrict__ w,
                                                const float* __restrict__ mod,
                                                int shOff, int scOff, int useMod,
                                                __half* __restrict__ out) {
    int row = blockIdx.x * 8 + (threadIdx.x >> 5);
    int lane = threadIdx.x & 31;
    int b = row >> 10;
    const float* xr = x + (size_t)row * DD;
    float v[32];
    float s = 0.f, s2 = 0.f;
    #pragma unroll
    for (int j = 0; j < 8; j++) {
        float4 t = *(const float4*)(xr + lane * 4 + j * 128);
        v[4 * j] = t.x; v[4 * j + 1] = t.y; v[4 * j + 2] = t.z; v[4 * j + 3] = t.w;
        s += t.x + t.y + t.z + t.w;
        s2 = fmaf(t.x, t.x, fmaf(t.y, t.y, fmaf(t.z, t.z, fmaf(t.w, t.w, s2))));
    }
    #pragma unroll
    for (int o = 16; o; o >>= 1) {
        s  += __shfl_xor_sync(0xffffffffu, s, o);
        s2 += __shfl_xor_sync(0xffffffffu, s2, o);
    }
    float mu = s * (1.0f / DD);
    float var = s2 * (1.0f / DD) - mu * mu;
    float rs = rsqrtf(var + 1e-5f);
    __half* orow = out + (size_t)row * DD;
    #pragma unroll
    for (int j = 0; j < 8; j++) {
        int d = lane * 4 + j * 128;
        float4 wv = *(const float4*)(w + d);
        float y0 = (v[4 * j] - mu) * rs * wv.x;
        float y1 = (v[4 * j + 1] - mu) * rs * wv.y;
        float y2 = (v[4 * j + 2] - mu) * rs * wv.z;
        float y3 = (v[4 * j + 3] - mu) * rs * wv.w;
        if (useMod) {
            float4 sc = *(const float4*)(mod + b * SIXD + scOff + d);
            float4 sh = *(const float4*)(mod + b * SIXD + shOff + d);
            y0 = y0 * (1.0f + sc.x) + sh.x;
            y1 = y1 * (1.0f + sc.y) + sh.y;
            y2 = y2 * (1.0f + sc.z) + sh.z;
            y3 = y3 * (1.0f + sc.w) + sh.w;
        }
        *(half2*)(orow + d) = __floats2half2_rn(y0, y1);
        *(half2*)(orow + d + 2) = __floats2half2_rn(y2, y3);
    }
}

// RoPE, half2/float2 vectorized. threads = rows * HH * 16.
__global__ void __launch_bounds__(256) rope_h_k(__half* __restrict__ x,
                                                const float* __restrict__ cosp,
                                                const float* __restrict__ sinp,
                                                int rowStride) {
    int idx = blockIdx.x * 256 + threadIdx.x;
    int d2 = idx & 15;
    int h = (idx >> 4) & 15;
    int rs = idx >> 8;
    int s = rs & 1023;
    __half* p = x + (size_t)rs * rowStride + h * HD + 2 * d2;
    half2 lo = *(half2*)p;
    half2 hi = *(half2*)(p + 32);
    float x1a = __half2float(lo.x), x1b = __half2float(lo.y);
    float x2a = __half2float(hi.x), x2b = __half2float(hi.y);
    float2 c1 = *(const float2*)(cosp + s * HD + 2 * d2);
    float2 s1 = *(const float2*)(sinp + s * HD + 2 * d2);
    float2 c2 = *(const float2*)(cosp + s * HD + 32 + 2 * d2);
    float2 s2v = *(const float2*)(sinp + s * HD + 32 + 2 * d2);
    *(half2*)p = __floats2half2_rn(x1a * c1.x - x2a * s1.x, x1b * c1.y - x2b * s1.y);
    *(half2*)(p + 32) = __floats2half2_rn(x2a * c2.x + x1a * s2v.x, x2b * c2.y + x1b * s2v.y);
}

// ================= host =================
extern "C" void kernel_launch(void* const* d_in, const int* in_sizes, int n_in,
                              void* d_out, int out_size) {
    const float* q_x    = (const float*)d_in[0];
    const float* kv_x   = (const float*)d_in[1];
    const float* t_cond = (const float*)d_in[2];
    const float* cos_q  = (const float*)d_in[3];
    const float* sin_q  = (const float*)d_in[4];
    const float* cos_k  = (const float*)d_in[5];
    const float* sin_k  = (const float*)d_in[6];
    const int*   grp    = (const int*)d_in[7];
    const void*  en     = d_in[8];
    const float* qn_w   = (const float*)d_in[9];
    const float* kvn_w  = (const float*)d_in[10];
    const float* n2_w   = (const float*)d_in[11];
    const float* Wq     = (const float*)d_in[12];
    const float* Wkv    = (const float*)d_in[13];
    const float* Wo     = (const float*)d_in[14];
    const float* W1     = (const float*)d_in[15];
    const float* b1     = (const float*)d_in[16];
    const float* W2     = (const float*)d_in[17];
    const float* b2     = (const float*)d_in[18];
    const float* adaW   = (const float*)d_in[19];
    const float* adab   = (const float*)d_in[20];
    float* out = (float*)d_out;

    float *mod, *x;
    __half *qn_h, *kvn_h, *q_h, *kv_h, *attn_h, *hh, *h1_h;
    __half *wq_h, *wkv_h, *wo_h, *w1_h, *w2_h;
    cudaGetSymbolAddress((void**)&mod,    g_mod);
    cudaGetSymbolAddress((void**)&x,      g_x);
    cudaGetSymbolAddress((void**)&qn_h,   g_qn_h);
    cudaGetSymbolAddress((void**)&kvn_h,  g_kvn_h);
    cudaGetSymbolAddress((void**)&q_h,    g_q_h);
    cudaGetSymbolAddress((void**)&kv_h,   g_kv_h);
    cudaGetSymbolAddress((void**)&attn_h, g_attn_h);
    cudaGetSymbolAddress((void**)&hh,     g_hh);
    cudaGetSymbolAddress((void**)&h1_h,   g_h1_h);
    cudaGetSymbolAddress((void**)&wq_h,   g_wq_h);
    cudaGetSymbolAddress((void**)&wkv_h,  g_wkv_h);
    cudaGetSymbolAddress((void**)&wo_h,   g_wo_h);
    cudaGetSymbolAddress((void**)&w1_h,   g_w1_h);
    cudaGetSymbolAddress((void**)&w2_h,   g_w2_h);

    cudaFuncSetAttribute(gemm_h<0>, cudaFuncAttributeMaxDynamicSharedMemorySize, GSM_BYTES);
    cudaFuncSetAttribute(gemm_h<1>, cudaFuncAttributeMaxDynamicSharedMemorySize, GSM_BYTES);
    cudaFuncSetAttribute(gemm_h<2>, cudaFuncAttributeMaxDynamicSharedMemorySize, GSM_BYTES);
    cudaFuncSetAttribute(flash_h, cudaFuncAttributeMaxDynamicSharedMemorySize, FL_BYTES);

    detect_en_k<<<1, 1024>>>((const int*)en);
    mod_k<<<BB * (SIXD / 256), 256>>>(t_cond, adaW, adab, mod);

    // weight conversion (16 elems/thread)
    wcvt_k<<<DD * DD / 4096, 256>>>(Wq, wq_h);
    wcvt_k<<<DD * 2 * DD / 4096, 256>>>(Wkv, wkv_h);
    wcvt_k<<<DD * DD / 4096, 256>>>(Wo, wo_h);
    wcvt_k<<<DD * MRD / 4096, 256>>>(W1, w1_h);
    wcvt_k<<<MRD * DD / 4096, 256>>>(W2, w2_h);

    ln_mod_k<<<NBS / 8, 256>>>(q_x, qn_w, mod, 0, DD, 1, qn_h);
    ln_mod_k<<<NBS / 8, 256>>>(kv_x, kvn_w, mod, 0, 0, 0, kvn_h);

    gemm_h<0><<<dim3(8, 32), 256, GSM_BYTES>>>(
        qn_h, wq_h, q_h, DD, DD, DD, DD, nullptr, nullptr, 0, nullptr, nullptr);
    gemm_h<0><<<dim3(16, 32), 256, GSM_BYTES>>>(
        kvn_h, wkv_h, kv_h, DD, DD, 2 * DD, 2 * DD, nullptr, nullptr, 0, nullptr, nullptr);

    rope_h_k<<<(NBS * HH * 16) / 256, 256>>>(q_h, cos_q, sin_q, DD);
    rope_h_k<<<(NBS * HH * 16) / 256, 256>>>(kv_h, cos_k, sin_k, 2 * DD);

    flash_h<<<dim3(SS / 128, BB * HH), 256, FL_BYTES>>>(q_h, kv_h, grp, attn_h);

    gemm_h<2><<<dim3(8, 32), 256, GSM_BYTES>>>(
        attn_h, wo_h, x, DD, DD, DD, DD, nullptr, mod, 2 * DD, en, q_x);

    ln_mod_k<<<NBS / 8, 256>>>(x, n2_w, mod, 3 * DD, 4 * DD, 1, hh);

    gemm_h<1><<<dim3(32, 32), 256, GSM_BYTES>>>(
        hh, w1_h, h1_h, DD, DD, MRD, MRD, b1, nullptr, 0, nullptr, nullptr);
    gemm_h<2><<<dim3(8, 32), 256, GSM_BYTES>>>(
        h1_h, w2_h, out, MRD, MRD, DD, DD, b2, mod, 5 * DD, en, x);
}

// round 11
// speedup vs baseline: 5.9600x; 1.0007x over previous
#include <cuda_runtime.h>
#include <cuda_fp16.h>
#include <cstdint>

// Problem constants
#define BB 4
#define SS 1024
#define KK 1024
#define DD 1024
#define HH 16
#define HD 64
#define MRD 4096
#define SIXD 6144
#define NBS 4096
#define INV_SQRT_HD 0.125f
#define GELU_C 0.7978845608028654f

// ---------------- scratch ----------------
__device__ __align__(16) float  g_mod[BB * SIXD];
__device__ __align__(16) float  g_x[NBS * DD];
__device__ __align__(16) __half g_qn_h[NBS * DD];
__device__ __align__(16) __half g_kvn_h[NBS * DD];
__device__ __align__(16) __half g_q_h[NBS * DD];
__device__ __align__(16) __half g_kv_h[NBS * 2 * DD];
__device__ __align__(16) __half g_attn_h[NBS * DD];
__device__ __align__(16) __half g_hh[NBS * DD];
__device__ __align__(16) __half g_h1_h[(size_t)NBS * MRD];
__device__ __align__(16) __half g_wq_h[DD * DD];
__device__ __align__(16) __half g_wkv_h[DD * 2 * DD];
__device__ __align__(16) __half g_wo_h[DD * DD];
__device__ __align__(16) __half g_w1_h[DD * MRD];
__device__ __align__(16) __half g_w2_h[MRD * DD];
__device__ int    g_enIsByte;

// ================= PTX helpers =================
__device__ __forceinline__ uint32_t smem_u32(const void* p) {
    uint32_t a;
    asm("{ .reg .u64 t; cvta.to.shared.u64 t, %1; cvt.u32.u64 %0, t; }" : "=r"(a) : "l"(p));
    return a;
}
#define CP_ASYNC16(sa, ga) \
    asm volatile("cp.async.ca.shared.global [%0], [%1], 16;" :: "r"(sa), "l"(ga) : "memory")
#define CP_COMMIT() asm volatile("cp.async.commit_group;" ::: "memory")
#define CP_WAIT0()  asm volatile("cp.async.wait_group 0;" ::: "memory")
#define CP_WAIT1()  asm volatile("cp.async.wait_group 1;" ::: "memory")

#define LDSM_X4(d0, d1, d2, d3, addr)                                          \
    asm volatile("ldmatrix.sync.aligned.m8n8.x4.shared.b16 {%0,%1,%2,%3}, [%4];" \
        : "=r"(d0), "=r"(d1), "=r"(d2), "=r"(d3) : "r"(addr))
#define LDSM_X4_T(d0, d1, d2, d3, addr)                                        \
    asm volatile("ldmatrix.sync.aligned.m8n8.x4.trans.shared.b16 {%0,%1,%2,%3}, [%4];" \
        : "=r"(d0), "=r"(d1), "=r"(d2), "=r"(d3) : "r"(addr))

__device__ __forceinline__ void mma_f16(float* c, uint32_t a0, uint32_t a1,
                                        uint32_t a2, uint32_t a3,
                                        uint32_t b0, uint32_t b1) {
    asm volatile(
        "mma.sync.aligned.m16n8k16.row.col.f32.f16.f16.f32 "
        "{%0,%1,%2,%3}, {%4,%5,%6,%7}, {%8,%9}, {%0,%1,%2,%3};"
        : "+f"(c[0]), "+f"(c[1]), "+f"(c[2]), "+f"(c[3])
        : "r"(a0), "r"(a1), "r"(a2), "r"(a3), "r"(b0), "r"(b1));
}
__device__ __forceinline__ float gelu_f(float v) {
    float u = GELU_C * (v + 0.044715f * v * v * v);
    u = fminf(fmaxf(u, -15.f), 15.f);
    float t = __expf(2.0f * u);
    return 0.5f * v * (1.0f + (t - 1.0f) / (t + 1.0f));
}

// ================= fp16 mma GEMM: BK=64, 2-stage, occ-2 (unchanged R8) =================
#define KPA 72
#define BPB 136
#define ASTG (128 * KPA)
#define BSTG (64 * BPB)
#define GSM_BYTES (2 * (ASTG + BSTG) * 2)   // 71680 bytes

template <int EPI>
__global__ void __launch_bounds__(256, 2) gemm_h(
    const __half* __restrict__ A, const __half* __restrict__ B, void* __restrict__ Cv,
    int Kd, int lda, int ldb, int ldc,
    const float* __restrict__ bias, const float* __restrict__ modv, int goff,
    const void* __restrict__ en, const float* __restrict__ basep)
{
    extern __shared__ __half smh[];
    const uint32_t smw = smem_u32(smh);

    const int tid = threadIdx.x;
    const int lane = tid & 31;
    const int wid = tid >> 5;
    const int wm = wid >> 2, wn = wid & 3;
    const int lq = lane >> 2, lr = lane & 3;
    const int rsel = lane & 15;
    const int ksel = (lane >> 4) * 8;

    const int row0 = blockIdx.y * 128, col0 = blockIdx.x * 128;

    float acc[4][4][4];
    #pragma unroll
    for (int i = 0; i < 4; i++)
        #pragma unroll
        for (int j = 0; j < 4; j++)
            #pragma unroll
            for (int e = 0; e < 4; e++) acc[i][j][e] = 0.f;

    const int nk = Kd / 64;

    auto load_stage = [&](int ks) {
        const int k0 = ks * 64;
        const int s = ks & 1;
        uint32_t abase = smw + (uint32_t)s * ASTG * 2;
        #pragma unroll
        for (int j = 0; j < 4; j++) {
            int idx = tid + 256 * j;
            int r = idx >> 3, c = idx & 7;
            CP_ASYNC16(abase + (uint32_t)(r * KPA + c * 8) * 2,
                       A + (size_t)(row0 + r) * lda + k0 + c * 8);
        }
        uint32_t bbase = smw + (uint32_t)(2 * ASTG + s * BSTG) * 2;
        #pragma unroll
        for (int j = 0; j < 4; j++) {
            int idx = tid + 256 * j;
            int r = idx >> 4, c = idx & 15;
            CP_ASYNC16(bbase + (uint32_t)(r * BPB + c * 8) * 2,
                       B + (size_t)(k0 + r) * ldb + col0 + c * 8);
        }
        CP_COMMIT();
    };

    load_stage(0);
    if (nk > 1) load_stage(1);

    for (int i = 0; i < nk; i++) {
        if (i == nk - 1) CP_WAIT0(); else CP_WAIT1();
        __syncthreads();

        const int s = i & 1;
        const uint32_t abase = smw + (uint32_t)s * ASTG * 2;
        const uint32_t bbase = smw + (uint32_t)(2 * ASTG + s * BSTG) * 2;

        #pragma unroll
        for (int kt = 0; kt < 4; kt++) {
            uint32_t af[4][4];
            #pragma unroll
            for (int mi = 0; mi < 4; mi++) {
                int rm = wm * 64 + mi * 16;
                LDSM_X4(af[mi][0], af[mi][1], af[mi][2], af[mi][3],
                        abase + (uint32_t)((rm + rsel) * KPA + kt * 16 + ksel) * 2);
            }
            #pragma unroll
            for (int njp = 0; njp < 2; njp++) {
                uint32_t b0, b1, b2, b3;
                int n0 = wn * 32 + njp * 16;
                LDSM_X4_T(b0, b1, b2, b3,
                          bbase + (uint32_t)((kt * 16 + rsel) * BPB + n0 + ksel) * 2);
                #pragma unroll
                for (int mi = 0; mi < 4; mi++) {
                    mma_f16(acc[mi][2 * njp],     af[mi][0], af[mi][1], af[mi][2], af[mi][3], b0, b1);
                    mma_f16(acc[mi][2 * njp + 1], af[mi][0], af[mi][1], af[mi][2], af[mi][3], b2, b3);
                }
            }
        }
        __syncthreads();
        if (i + 2 < nk) load_stage(i + 2);
    }

    #pragma unroll
    for (int mi = 0; mi < 4; mi++) {
        int rg = row0 + wm * 64 + mi * 16 + lq;
        float g0 = 0.f, g1 = 0.f;
        if (EPI == 2) {
            int e0 = g_enIsByte ? (int)((const unsigned char*)en)[rg] : ((const int*)en)[rg];
            int e1 = g_enIsByte ? (int)((const unsigned char*)en)[rg + 8] : ((const int*)en)[rg + 8];
            g0 = e0 ? 1.f : 0.f;
            g1 = e1 ? 1.f : 0.f;
        }
        #pragma unroll
        for (int nj = 0; nj < 4; nj++) {
            int cg = col0 + wn * 32 + nj * 8 + lr * 2;
            float v0 = acc[mi][nj][0], v1 = acc[mi][nj][1];
            float v2 = acc[mi][nj][2], v3 = acc[mi][nj][3];
            if (EPI == 0) {
                __half* C = (__half*)Cv;
                *(half2*)(C + (size_t)rg * ldc + cg) = __floats2half2_rn(v0, v1);
                *(half2*)(C + (size_t)(rg + 8) * ldc + cg) = __floats2half2_rn(v2, v3);
            } else if (EPI == 1) {
                float b0 = bias[cg], b1v = bias[cg + 1];
                __half* C = (__half*)Cv;
                *(half2*)(C + (size_t)rg * ldc + cg) =
                    __floats2half2_rn(gelu_f(v0 + b0), gelu_f(v1 + b1v));
                *(half2*)(C + (size_t)(rg + 8) * ldc + cg) =
                    __floats2half2_rn(gelu_f(v2 + b0), gelu_f(v3 + b1v));
            } else {
                float b0 = bias ? bias[cg] : 0.f, b1v = bias ? bias[cg + 1] : 0.f;
                int bb0 = rg >> 10, bb1 = (rg + 8) >> 10;
                float m00 = modv[bb0 * SIXD + goff + cg];
                float m01 = modv[bb0 * SIXD + goff + cg + 1];
                float m10 = modv[bb1 * SIXD + goff + cg];
                float m11 = modv[bb1 * SIXD + goff + cg + 1];
                float* C = (float*)Cv;
                *(float2*)(C + (size_t)rg * ldc + cg) = make_float2(
                    basep[(size_t)rg * DD + cg] + g0 * m00 * (v0 + b0),
                    basep[(size_t)rg * DD + cg + 1] + g0 * m01 * (v1 + b1v));
                *(float2*)(C + (size_t)(rg + 8) * ldc + cg) = make_float2(
                    basep[(size_t)(rg + 8) * DD + cg] + g1 * m10 * (v2 + b0),
                    basep[(size_t)(rg + 8) * DD + cg + 1] + g1 * m11 * (v3 + b1v));
            }
        }
    }
}

// ================= flash attention (fp16 mma, fused RoPE, occ-2) =================
#define FQP 72
#define FPP 136
#define FKO 9216
#define FVO 18432
#define FPO 27648
#define FL_BYTES (45056 * 2 + 1024)

__global__ void __launch_bounds__(256, 2) flash_h(
    const __half* __restrict__ q, const __half* __restrict__ kv,
    const int* __restrict__ grp, __half* __restrict__ attn,
    const float* __restrict__ cosq, const float* __restrict__ sinq,
    const float* __restrict__ cosk, const float* __restrict__ sink)
{
    extern __shared__ __half smh[];
    const uint32_t smw = smem_u32(smh);
    int* grpq = (int*)(smh + 45056);
    int* grpk = grpq + 128;

    const int tid = threadIdx.x;
    const int lane = tid & 31;
    const int wid = tid >> 5;
    const int wr0 = wid * 16;
    const int lq = lane >> 2, lr = lane & 3;
    const int rsel = lane & 15;
    const int ksel = (lane >> 4) * 8;
    const int nsel = (lane & 7) + (lane >> 4) * 8;
    const int kse2 = ((lane >> 3) & 1) * 8;

    const int qb = blockIdx.x;
    const int b = blockIdx.y >> 4;
    const int h = blockIdx.y & 15;

    // ---- load Q tile with fused RoPE (LDG -> rope -> STS) ----
    #pragma unroll
    for (int j = 0; j < 4; j++) {
        int idx = tid + 256 * j;
        int r = idx >> 3, c8 = idx & 7;
        int s = qb * 128 + r;
        const __half* row = q + (size_t)(b * SS + s) * DD + h * HD;
        uint4 own = *(const uint4*)(row + 8 * c8);
        uint4 par = *(const uint4*)(row + 8 * (c8 ^ 4));
        const __half* oh = (const __half*)&own;
        const __half* ph = (const __half*)&par;
        float4 cz0 = *(const float4*)(cosq + s * HD + 8 * c8);
        float4 cz1 = *(const float4*)(cosq + s * HD + 8 * c8 + 4);
        float4 sz0 = *(const float4*)(sinq + s * HD + 8 * c8);
        float4 sz1 = *(const float4*)(sinq + s * HD + 8 * c8 + 4);
        const float* cz = (const float*)&cz0;   // cz0,cz1 contiguous on stack
        float czv[8] = {cz0.x, cz0.y, cz0.z, cz0.w, cz1.x, cz1.y, cz1.z, cz1.w};
        float szv[8] = {sz0.x, sz0.y, sz0.z, sz0.w, sz1.x, sz1.y, sz1.z, sz1.w};
        (void)cz;
        float sgn = (c8 & 4) ? 1.f : -1.f;
        __half res[8];
        #pragma unroll
        for (int e = 0; e < 8; e++) {
            float x1 = __half2float(oh[e]);
            float x2 = __half2float(ph[e]);
            res[e] = __float2half_rn(x1 * czv[e] + sgn * x2 * szv[e]);
        }
        *(uint4*)(smh + r * FQP + 8 * c8) = *(uint4*)res;
    }
    if (tid < 128) grpq[tid] = grp[b * 1024 + qb * 128 + tid];

    float m0 = -3.0e38f, m1 = -3.0e38f, l0 = 0.f, l1 = 0.f;
    float oacc[8][4];
    #pragma unroll
    for (int j = 0; j < 8; j++)
        #pragma unroll
        for (int e = 0; e < 4; e++) oacc[j][e] = 0.f;

    for (int kc = 0; kc < 8; kc++) {
        // ---- V chunk via cp.async ----
        #pragma unroll
        for (int j = 0; j < 4; j++) {
            int idx = tid + 256 * j;
            int r = idx >> 3, c = idx & 7;
            CP_ASYNC16(smw + (uint32_t)(FVO + r * FQP + c * 8) * 2,
                       kv + (size_t)(b * 1024 + kc * 128 + r) * (2 * DD) + DD + h * HD + c * 8);
        }
        CP_COMMIT();
        // ---- K chunk with fused RoPE ----
        #pragma unroll
        for (int j = 0; j < 4; j++) {
            int idx = tid + 256 * j;
            int r = idx >> 3, c8 = idx & 7;
            int s = kc * 128 + r;
            const __half* row = kv + (size_t)(b * 1024 + s) * (2 * DD) + h * HD;
            uint4 own = *(const uint4*)(row + 8 * c8);
            uint4 par = *(const uint4*)(row + 8 * (c8 ^ 4));
            const __half* oh = (const __half*)&own;
            const __half* ph = (const __half*)&par;
            float4 cz0 = *(const float4*)(cosk + s * HD + 8 * c8);
            float4 cz1 = *(const float4*)(cosk + s * HD + 8 * c8 + 4);
            float4 sz0 = *(const float4*)(sink + s * HD + 8 * c8);
            float4 sz1 = *(const float4*)(sink + s * HD + 8 * c8 + 4);
            float czv[8] = {cz0.x, cz0.y, cz0.z, cz0.w, cz1.x, cz1.y, cz1.z, cz1.w};
            float szv[8] = {sz0.x, sz0.y, sz0.z, sz0.w, sz1.x, sz1.y, sz1.z, sz1.w};
            float sgn = (c8 & 4) ? 1.f : -1.f;
            __half res[8];
            #pragma unroll
            for (int e = 0; e < 8; e++) {
                float x1 = __half2float(oh[e]);
                float x2 = __half2float(ph[e]);
                res[e] = __float2half_rn(x1 * czv[e] + sgn * x2 * szv[e]);
            }
            *(uint4*)(smh + FKO + r * FQP + 8 * c8) = *(uint4*)res;
        }
        if (tid < 128) grpk[tid] = grp[b * 1024 + kc * 128 + tid];
        CP_WAIT0();
        __syncthreads();

        float sacc[16][4];
        #pragma unroll
        for (int nj = 0; nj < 16; nj++)
            #pragma unroll
            for (int e = 0; e < 4; e++) sacc[nj][e] = 0.f;

        #pragma unroll
        for (int kt = 0; kt < 4; kt++) {
            uint32_t a0, a1, a2, a3;
            LDSM_X4(a0, a1, a2, a3,
                    smw + (uint32_t)((wr0 + rsel) * FQP + kt * 16 + ksel) * 2);
            #pragma unroll
            for (int njp = 0; njp < 8; njp++) {
                uint32_t b0, b1, b2, b3;
                LDSM_X4(b0, b1, b2, b3,
                        smw + (uint32_t)(FKO + (njp * 16 + nsel) * FQP + kt * 16 + kse2) * 2);
                mma_f16(sacc[2 * njp],     a0, a1, a2, a3, b0, b1);
                mma_f16(sacc[2 * njp + 1], a0, a1, a2, a3, b2, b3);
            }
        }

        int gq0 = grpq[wr0 + lq], gq1 = grpq[wr0 + lq + 8];
        float rm0 = -3.0e38f, rm1 = -3.0e38f;
        #pragma unroll
        for (int nj = 0; nj < 16; nj++) {
            int c0i = nj * 8 + 2 * lr;
            int gk0 = grpk[c0i], gk1 = grpk[c0i + 1];
            float s0 = (gk0 != gq0) ? sacc[nj][0] * INV_SQRT_HD : -1.0e9f;
            float s1 = (gk1 != gq0) ? sacc[nj][1] * INV_SQRT_HD : -1.0e9f;
            float s2 = (gk0 != gq1) ? sacc[nj][2] * INV_SQRT_HD : -1.0e9f;
            float s3 = (gk1 != gq1) ? sacc[nj][3] * INV_SQRT_HD : -1.0e9f;
            sacc[nj][0] = s0; sacc[nj][1] = s1; sacc[nj][2] = s2; sacc[nj][3] = s3;
            rm0 = fmaxf(rm0, fmaxf(s0, s1));
            rm1 = fmaxf(rm1, fmaxf(s2, s3));
        }
        rm0 = fmaxf(rm0, __shfl_xor_sync(0xffffffffu, rm0, 1));
        rm0 = fmaxf(rm0, __shfl_xor_sync(0xffffffffu, rm0, 2));
        rm1 = fmaxf(rm1, __shfl_xor_sync(0xffffffffu, rm1, 1));
        rm1 = fmaxf(rm1, __shfl_xor_sync(0xffffffffu, rm1, 2));
        float mn0 = fmaxf(m0, rm0), mn1 = fmaxf(m1, rm1);
        float al0 = __expf(m0 - mn0), al1 = __expf(m1 - mn1);

        __half* Ps = smh + FPO;
        float ps0 = 0.f, ps1 = 0.f;
        #pragma unroll
        for (int nj = 0; nj < 16; nj++) {
            float e0 = __expf(sacc[nj][0] - mn0);
            float e1 = __expf(sacc[nj][1] - mn0);
            float e2 = __expf(sacc[nj][2] - mn1);
            float e3 = __expf(sacc[nj][3] - mn1);
            ps0 += e0 + e1; ps1 += e2 + e3;
            int c0i = nj * 8 + 2 * lr;
            *(half2*)(Ps + (wr0 + lq) * FPP + c0i) = __floats2half2_rn(e0, e1);
            *(half2*)(Ps + (wr0 + lq + 8) * FPP + c0i) = __floats2half2_rn(e2, e3);
        }
        ps0 += __shfl_xor_sync(0xffffffffu, ps0, 1);
        ps0 += __shfl_xor_sync(0xffffffffu, ps0, 2);
        ps1 += __shfl_xor_sync(0xffffffffu, ps1, 1);
        ps1 += __shfl_xor_sync(0xffffffffu, ps1, 2);
        l0 = l0 * al0 + ps0;
        l1 = l1 * al1 + ps1;
        m0 = mn0; m1 = mn1;

        #pragma unroll
        for (int nj = 0; nj < 8; nj++) {
            oacc[nj][0] *= al0; oacc[nj][1] *= al0;
            oacc[nj][2] *= al1; oacc[nj][3] *= al1;
        }
        __syncwarp();

        #pragma unroll
        for (int kt = 0; kt < 8; kt++) {
            uint32_t a0, a1, a2, a3;
            LDSM_X4(a0, a1, a2, a3,
                    smw + (uint32_t)(FPO + (wr0 + rsel) * FPP + kt * 16 + ksel) * 2);
            #pragma unroll
            for (int njp = 0; njp < 4; njp++) {
                uint32_t b0, b1, b2, b3;
                LDSM_X4_T(b0, b1, b2, b3,
                          smw + (uint32_t)(FVO + (kt * 16 + rsel) * FQP + njp * 16 + ksel) * 2);
                mma_f16(oacc[2 * njp],     a0, a1, a2, a3, b0, b1);
                mma_f16(oacc[2 * njp + 1], a0, a1, a2, a3, b2, b3);
            }
        }
        __syncthreads();
    }

    float il0 = 1.0f / l0, il1 = 1.0f / l1;
    int r0 = b * 1024 + qb * 128 + wr0 + lq;
    #pragma unroll
    for (int nj = 0; nj < 8; nj++) {
        int cg = h * HD + nj * 8 + 2 * lr;
        *(half2*)(attn + (size_t)r0 * DD + cg) =
            __floats2half2_rn(oacc[nj][0] * il0, oacc[nj][1] * il0);
        *(half2*)(attn + (size_t)(r0 + 8) * DD + cg) =
            __floats2half2_rn(oacc[nj][2] * il1, oacc[nj][3] * il1);
    }
}

// ================= small kernels =================
__global__ void __launch_bounds__(1024) detect_en_k(const int* __restrict__ en32) {
    __shared__ int sh[32];
    int v = en32[threadIdx.x];
    int f = (v & ~1) ? 1 : 0;
    #pragma unroll
    for (int o = 16; o; o >>= 1) f |= __shfl_xor_sync(0xffffffffu, f, o);
    if ((threadIdx.x & 31) == 0) sh[threadIdx.x >> 5] = f;
    __syncthreads();
    if (threadIdx.x == 0) {
        int t = 0;
        #pragma unroll
        for (int i = 0; i < 32; i++) t |= sh[i];
        g_enIsByte = t;
    }
}

// all 5 weight conversions in one launch; segment by blockIdx
__global__ void __launch_bounds__(256) wcvt_all_k(
    const float* __restrict__ s0, __half* __restrict__ d0,
    const float* __restrict__ s1, __half* __restrict__ d1,
    const float* __restrict__ s2, __half* __restrict__ d2,
    const float* __restrict__ s3, __half* __restrict__ d3,
    const float* __restrict__ s4, __half* __restrict__ d4)
{
    int bx = blockIdx.x;
    const float* src; __half* dst; int off;
    if (bx < 256)       { src = s0; dst = d0; off = bx; }
    else if (bx < 768)  { src = s1; dst = d1; off = bx - 256; }
    else if (bx < 1024) { src = s2; dst = d2; off = bx - 768; }
    else if (bx < 2048) { src = s3; dst = d3; off = bx - 1024; }
    else                { src = s4; dst = d4; off = bx - 2048; }
    size_t base = ((size_t)off * 256 + threadIdx.x) * 16;
    #pragma unroll
    for (int j = 0; j < 4; j++) {
        float4 v = *(const float4*)(src + base + 4 * j);
        half2* d = (half2*)(dst + base + 4 * j);
        d[0] = __floats2half2_rn(v.x, v.y);
        d[1] = __floats2half2_rn(v.z, v.w);
    }
}

__global__ void __launch_bounds__(256) mod_k(const float* __restrict__ t_cond,
                                             const float* __restrict__ adaW,
                                             const float* __restrict__ adab,
                                             float* __restrict__ mod) {
    __shared__ float tc[1024];
    int b  = blockIdx.x / 24;
    int cg = blockIdx.x % 24;
    for (int i = threadIdx.x; i < 1024; i += 256) tc[i] = t_cond[b * 1024 + i];
    __syncthreads();
    int col = cg * 256 + threadIdx.x;
    float acc = adab[col];
    #pragma unroll 4
    for (int i = 0; i < 1024; i++) acc = fmaf(tc[i], adaW[(size_t)i * SIXD + col], acc);
    mod[b * SIXD + col] = acc;
}

// warp-per-row LayerNorm -> fp16 (+ optional adaLN)
__global__ void __launch_bounds__(256) ln_mod_k(const float* __restrict__ x,
                                                const float* __restrict__ w,
                                                const float* __restrict__ mod,
                                                int shOff, int scOff, int useMod,
                                                __half* __restrict__ out) {
    int row = blockIdx.x * 8 + (threadIdx.x >> 5);
    int lane = threadIdx.x & 31;
    int b = row >> 10;
    const float* xr = x + (size_t)row * DD;
    float v[32];
    float s = 0.f, s2 = 0.f;
    #pragma unroll
    for (int j = 0; j < 8; j++) {
        float4 t = *(const float4*)(xr + lane * 4 + j * 128);
        v[4 * j] = t.x; v[4 * j + 1] = t.y; v[4 * j + 2] = t.z; v[4 * j + 3] = t.w;
        s += t.x + t.y + t.z + t.w;
        s2 = fmaf(t.x, t.x, fmaf(t.y, t.y, fmaf(t.z, t.z, fmaf(t.w, t.w, s2))));
    }
    #pragma unroll
    for (int o = 16; o; o >>= 1) {
        s  += __shfl_xor_sync(0xffffffffu, s, o);
        s2 += __shfl_xor_sync(0xffffffffu, s2, o);
    }
    float mu = s * (1.0f / DD);
    float var = s2 * (1.0f / DD) - mu * mu;
    float rs = rsqrtf(var + 1e-5f);
    __half* orow = out + (size_t)row * DD;
    #pragma unroll
    for (int j = 0; j < 8; j++) {
        int d = lane * 4 + j * 128;
        float4 wv = *(const float4*)(w + d);
        float y0 = (v[4 * j] - mu) * rs * wv.x;
        float y1 = (v[4 * j + 1] - mu) * rs * wv.y;
        float y2 = (v[4 * j + 2] - mu) * rs * wv.z;
        float y3 = (v[4 * j + 3] - mu) * rs * wv.w;
        if (useMod) {
            float4 sc = *(const float4*)(mod + b * SIXD + scOff + d);
            float4 sh = *(const float4*)(mod + b * SIXD + shOff + d);
            y0 = y0 * (1.0f + sc.x) + sh.x;
            y1 = y1 * (1.0f + sc.y) + sh.y;
            y2 = y2 * (1.0f + sc.z) + sh.z;
            y3 = y3 * (1.0f + sc.w) + sh.w;
        }
        *(half2*)(orow + d) = __floats2half2_rn(y0, y1);
        *(half2*)(orow + d + 2) = __floats2half2_rn(y2, y3);
    }
}

// ================= host =================
extern "C" void kernel_launch(void* const* d_in, const int* in_sizes, int n_in,
                              void* d_out, int out_size) {
    const float* q_x    = (const float*)d_in[0];
    const float* kv_x   = (const float*)d_in[1];
    const float* t_cond = (const float*)d_in[2];
    const float* cos_q  = (const float*)d_in[3];
    const float* sin_q  = (const float*)d_in[4];
    const float* cos_k  = (const float*)d_in[5];
    const float* sin_k  = (const float*)d_in[6];
    const int*   grp    = (const int*)d_in[7];
    const void*  en     = d_in[8];
    const float* qn_w   = (const float*)d_in[9];
    const float* kvn_w  = (const float*)d_in[10];
    const float* n2_w   = (const float*)d_in[11];
    const float* Wq     = (const float*)d_in[12];
    const float* Wkv    = (const float*)d_in[13];
    const float* Wo     = (const float*)d_in[14];
    const float* W1     = (const float*)d_in[15];
    const float* b1     = (const float*)d_in[16];
    const float* W2     = (const float*)d_in[17];
    const float* b2     = (const float*)d_in[18];
    const float* adaW   = (const float*)d_in[19];
    const float* adab   = (const float*)d_in[20];
    float* out = (float*)d_out;

    float *mod, *x;
    __half *qn_h, *kvn_h, *q_h, *kv_h, *attn_h, *hh, *h1_h;
    __half *wq_h, *wkv_h, *wo_h, *w1_h, *w2_h;
    cudaGetSymbolAddress((void**)&mod,    g_mod);
    cudaGetSymbolAddress((void**)&x,      g_x);
    cudaGetSymbolAddress((void**)&qn_h,   g_qn_h);
    cudaGetSymbolAddress((void**)&kvn_h,  g_kvn_h);
    cudaGetSymbolAddress((void**)&q_h,    g_q_h);
    cudaGetSymbolAddress((void**)&kv_h,   g_kv_h);
    cudaGetSymbolAddress((void**)&attn_h, g_attn_h);
    cudaGetSymbolAddress((void**)&hh,     g_hh);
    cudaGetSymbolAddress((void**)&h1_h,   g_h1_h);
    cudaGetSymbolAddress((void**)&wq_h,   g_wq_h);
    cudaGetSymbolAddress((void**)&wkv_h,  g_wkv_h);
    cudaGetSymbolAddress((void**)&wo_h,   g_wo_h);
    cudaGetSymbolAddress((void**)&w1_h,   g_w1_h);
    cudaGetSymbolAddress((void**)&w2_h,   g_w2_h);

    cudaFuncSetAttribute(gemm_h<0>, cudaFuncAttributeMaxDynamicSharedMemorySize, GSM_BYTES);
    cudaFuncSetAttribute(gemm_h<1>, cudaFuncAttributeMaxDynamicSharedMemorySize, GSM_BYTES);
    cudaFuncSetAttribute(gemm_h<2>, cudaFuncAttributeMaxDynamicSharedMemorySize, GSM_BYTES);
    cudaFuncSetAttribute(flash_h, cudaFuncAttributeMaxDynamicSharedMemorySize, FL_BYTES);

    detect_en_k<<<1, 1024>>>((const int*)en);
    mod_k<<<BB * (SIXD / 256), 256>>>(t_cond, adaW, adab, mod);

    // all weight conversions, one launch
    wcvt_all_k<<<3072, 256>>>(Wq, wq_h, Wkv, wkv_h, Wo, wo_h, W1, w1_h, W2, w2_h);

    ln_mod_k<<<NBS / 8, 256>>>(q_x, qn_w, mod, 0, DD, 1, qn_h);
    ln_mod_k<<<NBS / 8, 256>>>(kv_x, kvn_w, mod, 0, 0, 0, kvn_h);

    gemm_h<0><<<dim3(8, 32), 256, GSM_BYTES>>>(
        qn_h, wq_h, q_h, DD, DD, DD, DD, nullptr, nullptr, 0, nullptr, nullptr);
    gemm_h<0><<<dim3(16, 32), 256, GSM_BYTES>>>(
        kvn_h, wkv_h, kv_h, DD, DD, 2 * DD, 2 * DD, nullptr, nullptr, 0, nullptr, nullptr);

    // fused attention (RoPE + scores + mask + softmax + PV)
    flash_h<<<dim3(SS / 128, BB * HH), 256, FL_BYTES>>>(
        q_h, kv_h, grp, attn_h, cos_q, sin_q, cos_k, sin_k);

    gemm_h<2><<<dim3(8, 32), 256, GSM_BYTES>>>(
        attn_h, wo_h, x, DD, DD, DD, DD, nullptr, mod, 2 * DD, en, q_x);

    ln_mod_k<<<NBS / 8, 256>>>(x, n2_w, mod, 3 * DD, 4 * DD, 1, hh);

    gemm_h<1><<<dim3(32, 32), 256, GSM_BYTES>>>(
        hh, w1_h, h1_h, DD, DD, MRD, MRD, b1, nullptr, 0, nullptr, nullptr);
    gemm_h<2><<<dim3(8, 32), 256, GSM_BYTES>>>(
        h1_h, w2_h, out, MRD, MRD, DD, DD, b2, mod, 5 * DD, en, x);
}

// round 12
// speedup vs baseline: 6.8939x; 1.1567x over previous
#include <cuda_runtime.h>
#include <cuda_fp16.h>
#include <cstdint>

// Problem constants
#define BB 4
#define SS 1024
#define KK 1024
#define DD 1024
#define HH 16
#define HD 64
#define MRD 4096
#define SIXD 6144
#define NBS 4096
#define INV_SQRT_HD 0.125f
#define GELU_C 0.7978845608028654f

// ---------------- scratch ----------------
__device__ __align__(16) float  g_mod[BB * SIXD];
__device__ __align__(16) float  g_x[NBS * DD];
__device__ __align__(16) __half g_qn_h[NBS * DD];
__device__ __align__(16) __half g_kvn_h[NBS * DD];
__device__ __align__(16) __half g_q_h[NBS * DD];
__device__ __align__(16) __half g_kv_h[NBS * 2 * DD];
__device__ __align__(16) __half g_attn_h[NBS * DD];
__device__ __align__(16) __half g_hh[NBS * DD];
__device__ __align__(16) __half g_h1_h[(size_t)NBS * MRD];
__device__ __align__(16) __half g_wq_h[DD * DD];
__device__ __align__(16) __half g_wkv_h[DD * 2 * DD];
__device__ __align__(16) __half g_wo_h[DD * DD];
__device__ __align__(16) __half g_w1_h[DD * MRD];
__device__ __align__(16) __half g_w2_h[MRD * DD];
__device__ int    g_enIsByte;

// ================= PTX helpers =================
__device__ __forceinline__ uint32_t smem_u32(const void* p) {
    uint32_t a;
    asm("{ .reg .u64 t; cvta.to.shared.u64 t, %1; cvt.u32.u64 %0, t; }" : "=r"(a) : "l"(p));
    return a;
}
#define CP_ASYNC16(sa, ga) \
    asm volatile("cp.async.ca.shared.global [%0], [%1], 16;" :: "r"(sa), "l"(ga) : "memory")
#define CP_COMMIT() asm volatile("cp.async.commit_group;" ::: "memory")
#define CP_WAIT0()  asm volatile("cp.async.wait_group 0;" ::: "memory")
#define CP_WAIT1()  asm volatile("cp.async.wait_group 1;" ::: "memory")

#define LDSM_X4(d0, d1, d2, d3, addr)                                          \
    asm volatile("ldmatrix.sync.aligned.m8n8.x4.shared.b16 {%0,%1,%2,%3}, [%4];" \
        : "=r"(d0), "=r"(d1), "=r"(d2), "=r"(d3) : "r"(addr))
#define LDSM_X4_T(d0, d1, d2, d3, addr)                                        \
    asm volatile("ldmatrix.sync.aligned.m8n8.x4.trans.shared.b16 {%0,%1,%2,%3}, [%4];" \
        : "=r"(d0), "=r"(d1), "=r"(d2), "=r"(d3) : "r"(addr))

__device__ __forceinline__ void mma_f16(float* c, uint32_t a0, uint32_t a1,
                                        uint32_t a2, uint32_t a3,
                                        uint32_t b0, uint32_t b1) {
    asm volatile(
        "mma.sync.aligned.m16n8k16.row.col.f32.f16.f16.f32 "
        "{%0,%1,%2,%3}, {%4,%5,%6,%7}, {%8,%9}, {%0,%1,%2,%3};"
        : "+f"(c[0]), "+f"(c[1]), "+f"(c[2]), "+f"(c[3])
        : "r"(a0), "r"(a1), "r"(a2), "r"(a3), "r"(b0), "r"(b1));
}
__device__ __forceinline__ float gelu_f(float v) {
    float u = GELU_C * (v + 0.044715f * v * v * v);
    u = fminf(fmaxf(u, -15.f), 15.f);
    float t = __expf(2.0f * u);
    return 0.5f * v * (1.0f + (t - 1.0f) / (t + 1.0f));
}

// ================= fp16 mma GEMM: BK=64, 2-stage, occ-2 (unchanged) =================
#define KPA 72
#define BPB 136
#define ASTG (128 * KPA)
#define BSTG (64 * BPB)
#define GSM_BYTES (2 * (ASTG + BSTG) * 2)   // 71680 bytes

template <int EPI>
__global__ void __launch_bounds__(256, 2) gemm_h(
    const __half* __restrict__ A, const __half* __restrict__ B, void* __restrict__ Cv,
    int Kd, int lda, int ldb, int ldc,
    const float* __restrict__ bias, const float* __restrict__ modv, int goff,
    const void* __restrict__ en, const float* __restrict__ basep)
{
    extern __shared__ __half smh[];
    const uint32_t smw = smem_u32(smh);

    const int tid = threadIdx.x;
    const int lane = tid & 31;
    const int wid = tid >> 5;
    const int wm = wid >> 2, wn = wid & 3;
    const int lq = lane >> 2, lr = lane & 3;
    const int rsel = lane & 15;
    const int ksel = (lane >> 4) * 8;

    const int row0 = blockIdx.y * 128, col0 = blockIdx.x * 128;

    float acc[4][4][4];
    #pragma unroll
    for (int i = 0; i < 4; i++)
        #pragma unroll
        for (int j = 0; j < 4; j++)
            #pragma unroll
            for (int e = 0; e < 4; e++) acc[i][j][e] = 0.f;

    const int nk = Kd / 64;

    auto load_stage = [&](int ks) {
        const int k0 = ks * 64;
        const int s = ks & 1;
        uint32_t abase = smw + (uint32_t)s * ASTG * 2;
        #pragma unroll
        for (int j = 0; j < 4; j++) {
            int idx = tid + 256 * j;
            int r = idx >> 3, c = idx & 7;
            CP_ASYNC16(abase + (uint32_t)(r * KPA + c * 8) * 2,
                       A + (size_t)(row0 + r) * lda + k0 + c * 8);
        }
        uint32_t bbase = smw + (uint32_t)(2 * ASTG + s * BSTG) * 2;
        #pragma unroll
        for (int j = 0; j < 4; j++) {
            int idx = tid + 256 * j;
            int r = idx >> 4, c = idx & 15;
            CP_ASYNC16(bbase + (uint32_t)(r * BPB + c * 8) * 2,
                       B + (size_t)(k0 + r) * ldb + col0 + c * 8);
        }
        CP_COMMIT();
    };

    load_stage(0);
    if (nk > 1) load_stage(1);

    for (int i = 0; i < nk; i++) {
        if (i == nk - 1) CP_WAIT0(); else CP_WAIT1();
        __syncthreads();

        const int s = i & 1;
        const uint32_t abase = smw + (uint32_t)s * ASTG * 2;
        const uint32_t bbase = smw + (uint32_t)(2 * ASTG + s * BSTG) * 2;

        #pragma unroll
        for (int kt = 0; kt < 4; kt++) {
            uint32_t af[4][4];
            #pragma unroll
            for (int mi = 0; mi < 4; mi++) {
                int rm = wm * 64 + mi * 16;
                LDSM_X4(af[mi][0], af[mi][1], af[mi][2], af[mi][3],
                        abase + (uint32_t)((rm + rsel) * KPA + kt * 16 + ksel) * 2);
            }
            #pragma unroll
            for (int njp = 0; njp < 2; njp++) {
                uint32_t b0, b1, b2, b3;
                int n0 = wn * 32 + njp * 16;
                LDSM_X4_T(b0, b1, b2, b3,
                          bbase + (uint32_t)((kt * 16 + rsel) * BPB + n0 + ksel) * 2);
                #pragma unroll
                for (int mi = 0; mi < 4; mi++) {
                    mma_f16(acc[mi][2 * njp],     af[mi][0], af[mi][1], af[mi][2], af[mi][3], b0, b1);
                    mma_f16(acc[mi][2 * njp + 1], af[mi][0], af[mi][1], af[mi][2], af[mi][3], b2, b3);
                }
            }
        }
        __syncthreads();
        if (i + 2 < nk) load_stage(i + 2);
    }

    #pragma unroll
    for (int mi = 0; mi < 4; mi++) {
        int rg = row0 + wm * 64 + mi * 16 + lq;
        float g0 = 0.f, g1 = 0.f;
        if (EPI == 2) {
            int e0 = g_enIsByte ? (int)((const unsigned char*)en)[rg] : ((const int*)en)[rg];
            int e1 = g_enIsByte ? (int)((const unsigned char*)en)[rg + 8] : ((const int*)en)[rg + 8];
            g0 = e0 ? 1.f : 0.f;
            g1 = e1 ? 1.f : 0.f;
        }
        #pragma unroll
        for (int nj = 0; nj < 4; nj++) {
            int cg = col0 + wn * 32 + nj * 8 + lr * 2;
            float v0 = acc[mi][nj][0], v1 = acc[mi][nj][1];
            float v2 = acc[mi][nj][2], v3 = acc[mi][nj][3];
            if (EPI == 0) {
                __half* C = (__half*)Cv;
                *(half2*)(C + (size_t)rg * ldc + cg) = __floats2half2_rn(v0, v1);
                *(half2*)(C + (size_t)(rg + 8) * ldc + cg) = __floats2half2_rn(v2, v3);
            } else if (EPI == 1) {
                float b0 = bias[cg], b1v = bias[cg + 1];
                __half* C = (__half*)Cv;
                *(half2*)(C + (size_t)rg * ldc + cg) =
                    __floats2half2_rn(gelu_f(v0 + b0), gelu_f(v1 + b1v));
                *(half2*)(C + (size_t)(rg + 8) * ldc + cg) =
                    __floats2half2_rn(gelu_f(v2 + b0), gelu_f(v3 + b1v));
            } else {
                float b0 = bias ? bias[cg] : 0.f, b1v = bias ? bias[cg + 1] : 0.f;
                int bb0 = rg >> 10, bb1 = (rg + 8) >> 10;
                float m00 = modv[bb0 * SIXD + goff + cg];
                float m01 = modv[bb0 * SIXD + goff + cg + 1];
                float m10 = modv[bb1 * SIXD + goff + cg];
                float m11 = modv[bb1 * SIXD + goff + cg + 1];
                float* C = (float*)Cv;
                *(float2*)(C + (size_t)rg * ldc + cg) = make_float2(
                    basep[(size_t)rg * DD + cg] + g0 * m00 * (v0 + b0),
                    basep[(size_t)rg * DD + cg + 1] + g0 * m01 * (v1 + b1v));
                *(float2*)(C + (size_t)(rg + 8) * ldc + cg) = make_float2(
                    basep[(size_t)(rg + 8) * DD + cg] + g1 * m10 * (v2 + b0),
                    basep[(size_t)(rg + 8) * DD + cg + 1] + g1 * m11 * (v3 + b1v));
            }
        }
    }
}

// ================= flash attention (fp16 mma, fused RoPE, occ-2) — unchanged =================
#define FQP 72
#define FPP 136
#define FKO 9216
#define FVO 18432
#define FPO 27648
#define FL_BYTES (45056 * 2 + 1024)

__global__ void __launch_bounds__(256, 2) flash_h(
    const __half* __restrict__ q, const __half* __restrict__ kv,
    const int* __restrict__ grp, __half* __restrict__ attn,
    const float* __restrict__ cosq, const float* __restrict__ sinq,
    const float* __restrict__ cosk, const float* __restrict__ sink)
{
    extern __shared__ __half smh[];
    const uint32_t smw = smem_u32(smh);
    int* grpq = (int*)(smh + 45056);
    int* grpk = grpq + 128;

    const int tid = threadIdx.x;
    const int lane = tid & 31;
    const int wid = tid >> 5;
    const int wr0 = wid * 16;
    const int lq = lane >> 2, lr = lane & 3;
    const int rsel = lane & 15;
    const int ksel = (lane >> 4) * 8;
    const int nsel = (lane & 7) + (lane >> 4) * 8;
    const int kse2 = ((lane >> 3) & 1) * 8;

    const int qb = blockIdx.x;
    const int b = blockIdx.y >> 4;
    const int h = blockIdx.y & 15;

    #pragma unroll
    for (int j = 0; j < 4; j++) {
        int idx = tid + 256 * j;
        int r = idx >> 3, c8 = idx & 7;
        int s = qb * 128 + r;
        const __half* row = q + (size_t)(b * SS + s) * DD + h * HD;
        uint4 own = *(const uint4*)(row + 8 * c8);
        uint4 par = *(const uint4*)(row + 8 * (c8 ^ 4));
        const __half* oh = (const __half*)&own;
        const __half* ph = (const __half*)&par;
        float4 cz0 = *(const float4*)(cosq + s * HD + 8 * c8);
        float4 cz1 = *(const float4*)(cosq + s * HD + 8 * c8 + 4);
        float4 sz0 = *(const float4*)(sinq + s * HD + 8 * c8);
        float4 sz1 = *(const float4*)(sinq + s * HD + 8 * c8 + 4);
        float czv[8] = {cz0.x, cz0.y, cz0.z, cz0.w, cz1.x, cz1.y, cz1.z, cz1.w};
        float szv[8] = {sz0.x, sz0.y, sz0.z, sz0.w, sz1.x, sz1.y, sz1.z, sz1.w};
        float sgn = (c8 & 4) ? 1.f : -1.f;
        __half res[8];
        #pragma unroll
        for (int e = 0; e < 8; e++) {
            float x1 = __half2float(oh[e]);
            float x2 = __half2float(ph[e]);
            res[e] = __float2half_rn(x1 * czv[e] + sgn * x2 * szv[e]);
        }
        *(uint4*)(smh + r * FQP + 8 * c8) = *(uint4*)res;
    }
    if (tid < 128) grpq[tid] = grp[b * 1024 + qb * 128 + tid];

    float m0 = -3.0e38f, m1 = -3.0e38f, l0 = 0.f, l1 = 0.f;
    float oacc[8][4];
    #pragma unroll
    for (int j = 0; j < 8; j++)
        #pragma unroll
        for (int e = 0; e < 4; e++) oacc[j][e] = 0.f;

    for (int kc = 0; kc < 8; kc++) {
        #pragma unroll
        for (int j = 0; j < 4; j++) {
            int idx = tid + 256 * j;
            int r = idx >> 3, c = idx & 7;
            CP_ASYNC16(smw + (uint32_t)(FVO + r * FQP + c * 8) * 2,
                       kv + (size_t)(b * 1024 + kc * 128 + r) * (2 * DD) + DD + h * HD + c * 8);
        }
        CP_COMMIT();
        #pragma unroll
        for (int j = 0; j < 4; j++) {
            int idx = tid + 256 * j;
            int r = idx >> 3, c8 = idx & 7;
            int s = kc * 128 + r;
            const __half* row = kv + (size_t)(b * 1024 + s) * (2 * DD) + h * HD;
            uint4 own = *(const uint4*)(row + 8 * c8);
            uint4 par = *(const uint4*)(row + 8 * (c8 ^ 4));
            const __half* oh = (const __half*)&own;
            const __half* ph = (const __half*)&par;
            float4 cz0 = *(const float4*)(cosk + s * HD + 8 * c8);
            float4 cz1 = *(const float4*)(cosk + s * HD + 8 * c8 + 4);
            float4 sz0 = *(const float4*)(sink + s * HD + 8 * c8);
            float4 sz1 = *(const float4*)(sink + s * HD + 8 * c8 + 4);
            float czv[8] = {cz0.x, cz0.y, cz0.z, cz0.w, cz1.x, cz1.y, cz1.z, cz1.w};
            float szv[8] = {sz0.x, sz0.y, sz0.z, sz0.w, sz1.x, sz1.y, sz1.z, sz1.w};
            float sgn = (c8 & 4) ? 1.f : -1.f;
            __half res[8];
            #pragma unroll
            for (int e = 0; e < 8; e++) {
                float x1 = __half2float(oh[e]);
                float x2 = __half2float(ph[e]);
                res[e] = __float2half_rn(x1 * czv[e] + sgn * x2 * szv[e]);
            }
            *(uint4*)(smh + FKO + r * FQP + 8 * c8) = *(uint4*)res;
        }
        if (tid < 128) grpk[tid] = grp[b * 1024 + kc * 128 + tid];
        CP_WAIT0();
        __syncthreads();

        float sacc[16][4];
        #pragma unroll
        for (int nj = 0; nj < 16; nj++)
            #pragma unroll
            for (int e = 0; e < 4; e++) sacc[nj][e] = 0.f;

        #pragma unroll
        for (int kt = 0; kt < 4; kt++) {
            uint32_t a0, a1, a2, a3;
            LDSM_X4(a0, a1, a2, a3,
                    smw + (uint32_t)((wr0 + rsel) * FQP + kt * 16 + ksel) * 2);
            #pragma unroll
            for (int njp = 0; njp < 8; njp++) {
                uint32_t b0, b1, b2, b3;
                LDSM_X4(b0, b1, b2, b3,
                        smw + (uint32_t)(FKO + (njp * 16 + nsel) * FQP + kt * 16 + kse2) * 2);
                mma_f16(sacc[2 * njp],     a0, a1, a2, a3, b0, b1);
                mma_f16(sacc[2 * njp + 1], a0, a1, a2, a3, b2, b3);
            }
        }

        int gq0 = grpq[wr0 + lq], gq1 = grpq[wr0 + lq + 8];
        float rm0 = -3.0e38f, rm1 = -3.0e38f;
        #pragma unroll
        for (int nj = 0; nj < 16; nj++) {
            int c0i = nj * 8 + 2 * lr;
            int gk0 = grpk[c0i], gk1 = grpk[c0i + 1];
            float s0 = (gk0 != gq0) ? sacc[nj][0] * INV_SQRT_HD : -1.0e9f;
            float s1 = (gk1 != gq0) ? sacc[nj][1] * INV_SQRT_HD : -1.0e9f;
            float s2 = (gk0 != gq1) ? sacc[nj][2] * INV_SQRT_HD : -1.0e9f;
            float s3 = (gk1 != gq1) ? sacc[nj][3] * INV_SQRT_HD : -1.0e9f;
            sacc[nj][0] = s0; sacc[nj][1] = s1; sacc[nj][2] = s2; sacc[nj][3] = s3;
            rm0 = fmaxf(rm0, fmaxf(s0, s1));
            rm1 = fmaxf(rm1, fmaxf(s2, s3));
        }
        rm0 = fmaxf(rm0, __shfl_xor_sync(0xffffffffu, rm0, 1));
        rm0 = fmaxf(rm0, __shfl_xor_sync(0xffffffffu, rm0, 2));
        rm1 = fmaxf(rm1, __shfl_xor_sync(0xffffffffu, rm1, 1));
        rm1 = fmaxf(rm1, __shfl_xor_sync(0xffffffffu, rm1, 2));
        float mn0 = fmaxf(m0, rm0), mn1 = fmaxf(m1, rm1);
        float al0 = __expf(m0 - mn0), al1 = __expf(m1 - mn1);

        __half* Ps = smh + FPO;
        float ps0 = 0.f, ps1 = 0.f;
        #pragma unroll
        for (int nj = 0; nj < 16; nj++) {
            float e0 = __expf(sacc[nj][0] - mn0);
            float e1 = __expf(sacc[nj][1] - mn0);
            float e2 = __expf(sacc[nj][2] - mn1);
            float e3 = __expf(sacc[nj][3] - mn1);
            ps0 += e0 + e1; ps1 += e2 + e3;
            int c0i = nj * 8 + 2 * lr;
            *(half2*)(Ps + (wr0 + lq) * FPP + c0i) = __floats2half2_rn(e0, e1);
            *(half2*)(Ps + (wr0 + lq + 8) * FPP + c0i) = __floats2half2_rn(e2, e3);
        }
        ps0 += __shfl_xor_sync(0xffffffffu, ps0, 1);
        ps0 += __shfl_xor_sync(0xffffffffu, ps0, 2);
        ps1 += __shfl_xor_sync(0xffffffffu, ps1, 1);
        ps1 += __shfl_xor_sync(0xffffffffu, ps1, 2);
        l0 = l0 * al0 + ps0;
        l1 = l1 * al1 + ps1;
        m0 = mn0; m1 = mn1;

        #pragma unroll
        for (int nj = 0; nj < 8; nj++) {
            oacc[nj][0] *= al0; oacc[nj][1] *= al0;
            oacc[nj][2] *= al1; oacc[nj][3] *= al1;
        }
        __syncwarp();

        #pragma unroll
        for (int kt = 0; kt < 8; kt++) {
            uint32_t a0, a1, a2, a3;
            LDSM_X4(a0, a1, a2, a3,
                    smw + (uint32_t)(FPO + (wr0 + rsel) * FPP + kt * 16 + ksel) * 2);
            #pragma unroll
            for (int njp = 0; njp < 4; njp++) {
                uint32_t b0, b1, b2, b3;
                LDSM_X4_T(b0, b1, b2, b3,
                          smw + (uint32_t)(FVO + (kt * 16 + rsel) * FQP + njp * 16 + ksel) * 2);
                mma_f16(oacc[2 * njp],     a0, a1, a2, a3, b0, b1);
                mma_f16(oacc[2 * njp + 1], a0, a1, a2, a3, b2, b3);
            }
        }
        __syncthreads();
    }

    float il0 = 1.0f / l0, il1 = 1.0f / l1;
    int r0 = b * 1024 + qb * 128 + wr0 + lq;
    #pragma unroll
    for (int nj = 0; nj < 8; nj++) {
        int cg = h * HD + nj * 8 + 2 * lr;
        *(half2*)(attn + (size_t)r0 * DD + cg) =
            __floats2half2_rn(oacc[nj][0] * il0, oacc[nj][1] * il0);
        *(half2*)(attn + (size_t)(r0 + 8) * DD + cg) =
            __floats2half2_rn(oacc[nj][2] * il1, oacc[nj][3] * il1);
    }
}

// ================= small kernels =================
// adaLN modulation, single adaW pass for all 4 batches + en-dtype detect in block 96.
__global__ void __launch_bounds__(256) mod2_k(const float* __restrict__ t_cond,
                                              const float* __restrict__ adaW,
                                              const float* __restrict__ adab,
                                              float* __restrict__ mod,
                                              const int* __restrict__ en32) {
    if (blockIdx.x == 96) {
        __shared__ int shd[8];
        int f = 0;
        #pragma unroll
        for (int j = 0; j < 4; j++) {
            int v = en32[threadIdx.x * 4 + j];
            f |= (v & ~1) ? 1 : 0;
        }
        #pragma unroll
        for (int o = 16; o; o >>= 1) f |= __shfl_xor_sync(0xffffffffu, f, o);
        if ((threadIdx.x & 31) == 0) shd[threadIdx.x >> 5] = f;
        __syncthreads();
        if (threadIdx.x == 0) {
            int t = 0;
            #pragma unroll
            for (int i = 0; i < 8; i++) t |= shd[i];
            g_enIsByte = t;
        }
        return;
    }
    __shared__ float tc[4][1024];
    __shared__ float part[4][4][64];    // [kq][b][c]
    for (int i = threadIdx.x; i < 4096; i += 256)
        tc[i >> 10][i & 1023] = t_cond[i];
    __syncthreads();
    const int cc = blockIdx.x * 64;
    const int c = threadIdx.x & 63, kq = threadIdx.x >> 6;
    float a0 = 0.f, a1 = 0.f, a2 = 0.f, a3 = 0.f;
    const int kb = kq * 256;
    #pragma unroll 4
    for (int k = kb; k < kb + 256; k++) {
        float w = adaW[(size_t)k * SIXD + cc + c];
        a0 = fmaf(tc[0][k], w, a0);
        a1 = fmaf(tc[1][k], w, a1);
        a2 = fmaf(tc[2][k], w, a2);
        a3 = fmaf(tc[3][k], w, a3);
    }
    part[kq][0][c] = a0; part[kq][1][c] = a1;
    part[kq][2][c] = a2; part[kq][3][c] = a3;
    __syncthreads();
    if (kq < 4 && threadIdx.x < 64) {
        #pragma unroll
        for (int b = 0; b < 4; b++) {
            float s = part[0][b][c] + part[1][b][c] + part[2][b][c] + part[3][b][c];
            mod[b * SIXD + cc + c] = s + adab[cc + c];
        }
    }
}

// all 5 weight conversions in one launch
__global__ void __launch_bounds__(256) wcvt_all_k(
    const float* __restrict__ s0, __half* __restrict__ d0,
    const float* __restrict__ s1, __half* __restrict__ d1,
    const float* __restrict__ s2, __half* __restrict__ d2,
    const float* __restrict__ s3, __half* __restrict__ d3,
    const float* __restrict__ s4, __half* __restrict__ d4)
{
    int bx = blockIdx.x;
    const float* src; __half* dst; int off;
    if (bx < 256)       { src = s0; dst = d0; off = bx; }
    else if (bx < 768)  { src = s1; dst = d1; off = bx - 256; }
    else if (bx < 1024) { src = s2; dst = d2; off = bx - 768; }
    else if (bx < 2048) { src = s3; dst = d3; off = bx - 1024; }
    else                { src = s4; dst = d4; off = bx - 2048; }
    size_t base = ((size_t)off * 256 + threadIdx.x) * 16;
    #pragma unroll
    for (int j = 0; j < 4; j++) {
        float4 v = *(const float4*)(src + base + 4 * j);
        half2* d = (half2*)(dst + base + 4 * j);
        d[0] = __floats2half2_rn(v.x, v.y);
        d[1] = __floats2half2_rn(v.z, v.w);
    }
}

// block-per-row LN body (R7 form: v[4]/thread, block reduce) -> fp16 out
__device__ __forceinline__ void ln_row_body(const float* __restrict__ xr,
                                            const float* __restrict__ w,
                                            const float* __restrict__ mod,
                                            int b, int shOff, int scOff, int useMod,
                                            __half* __restrict__ orow, float* sh) {
    int tid = threadIdx.x;
    float v[4];
    float s = 0.f, s2 = 0.f;
    #pragma unroll
    for (int j = 0; j < 4; j++) {
        v[j] = xr[tid + j * 256];
        s += v[j];
        s2 = fmaf(v[j], v[j], s2);
    }
    // block reduce
    #pragma unroll
    for (int o = 16; o; o >>= 1) {
        s  += __shfl_xor_sync(0xffffffffu, s, o);
        s2 += __shfl_xor_sync(0xffffffffu, s2, o);
    }
    if ((tid & 31) == 0) { sh[tid >> 5] = s; sh[8 + (tid >> 5)] = s2; }
    __syncthreads();
    if (tid == 0) {
        float t = 0.f, t2 = 0.f;
        #pragma unroll
        for (int i = 0; i < 8; i++) { t += sh[i]; t2 += sh[8 + i]; }
        sh[16] = t; sh[17] = t2;
    }
    __syncthreads();
    float mu = sh[16] * (1.0f / DD);
    float var = sh[17] * (1.0f / DD) - mu * mu;
    float rs = rsqrtf(var + 1e-5f);
    #pragma unroll
    for (int j = 0; j < 4; j++) {
        int d = tid + j * 256;
        float y = (v[j] - mu) * rs * w[d];
        if (useMod) y = y * (1.0f + mod[b * SIXD + scOff + d]) + mod[b * SIXD + shOff + d];
        orow[d] = __float2half_rn(y);
    }
}

// merged: blocks [0,4096) -> LN(q_x)+msa-mod -> qn; [4096,8192) -> LN(kv_x) -> kvn
__global__ void __launch_bounds__(256) ln_pair_k(const float* __restrict__ xq,
                                                 const float* __restrict__ xkv,
                                                 const float* __restrict__ wq,
                                                 const float* __restrict__ wkv,
                                                 const float* __restrict__ mod,
                                                 __half* __restrict__ oq,
                                                 __half* __restrict__ okv) {
    __shared__ float sh[18];
    int half = blockIdx.x >> 12;
    int row = blockIdx.x & 4095;
    int b = row >> 10;
    if (half == 0)
        ln_row_body(xq + (size_t)row * DD, wq, mod, b, 0, DD, 1, oq + (size_t)row * DD, sh);
    else
        ln_row_body(xkv + (size_t)row * DD, wkv, mod, b, 0, 0, 0, okv + (size_t)row * DD, sh);
}

__global__ void __launch_bounds__(256) ln_one_k(const float* __restrict__ x,
                                                const float* __restrict__ w,
                                                const float* __restrict__ mod,
                                                int shOff, int scOff,
                                                __half* __restrict__ out) {
    __shared__ float sh[18];
    int row = blockIdx.x;
    int b = row >> 10;
    ln_row_body(x + (size_t)row * DD, w, mod, b, shOff, scOff, 1, out + (size_t)row * DD, sh);
}

// ================= host =================
extern "C" void kernel_launch(void* const* d_in, const int* in_sizes, int n_in,
                              void* d_out, int out_size) {
    const float* q_x    = (const float*)d_in[0];
    const float* kv_x   = (const float*)d_in[1];
    const float* t_cond = (const float*)d_in[2];
    const float* cos_q  = (const float*)d_in[3];
    const float* sin_q  = (const float*)d_in[4];
    const float* cos_k  = (const float*)d_in[5];
    const float* sin_k  = (const float*)d_in[6];
    const int*   grp    = (const int*)d_in[7];
    const void*  en     = d_in[8];
    const float* qn_w   = (const float*)d_in[9];
    const float* kvn_w  = (const float*)d_in[10];
    const float* n2_w   = (const float*)d_in[11];
    const float* Wq     = (const float*)d_in[12];
    const float* Wkv    = (const float*)d_in[13];
    const float* Wo     = (const float*)d_in[14];
    const float* W1     = (const float*)d_in[15];
    const float* b1     = (const float*)d_in[16];
    const float* W2     = (const float*)d_in[17];
    const float* b2     = (const float*)d_in[18];
    const float* adaW   = (const float*)d_in[19];
    const float* adab   = (const float*)d_in[20];
    float* out = (float*)d_out;

    float *mod, *x;
    __half *qn_h, *kvn_h, *q_h, *kv_h, *attn_h, *hh, *h1_h;
    __half *wq_h, *wkv_h, *wo_h, *w1_h, *w2_h;
    cudaGetSymbolAddress((void**)&mod,    g_mod);
    cudaGetSymbolAddress((void**)&x,      g_x);
    cudaGetSymbolAddress((void**)&qn_h,   g_qn_h);
    cudaGetSymbolAddress((void**)&kvn_h,  g_kvn_h);
    cudaGetSymbolAddress((void**)&q_h,    g_q_h);
    cudaGetSymbolAddress((void**)&kv_h,   g_kv_h);
    cudaGetSymbolAddress((void**)&attn_h, g_attn_h);
    cudaGetSymbolAddress((void**)&hh,     g_hh);
    cudaGetSymbolAddress((void**)&h1_h,   g_h1_h);
    cudaGetSymbolAddress((void**)&wq_h,   g_wq_h);
    cudaGetSymbolAddress((void**)&wkv_h,  g_wkv_h);
    cudaGetSymbolAddress((void**)&wo_h,   g_wo_h);
    cudaGetSymbolAddress((void**)&w1_h,   g_w1_h);
    cudaGetSymbolAddress((void**)&w2_h,   g_w2_h);

    cudaFuncSetAttribute(gemm_h<0>, cudaFuncAttributeMaxDynamicSharedMemorySize, GSM_BYTES);
    cudaFuncSetAttribute(gemm_h<1>, cudaFuncAttributeMaxDynamicSharedMemorySize, GSM_BYTES);
    cudaFuncSetAttribute(gemm_h<2>, cudaFuncAttributeMaxDynamicSharedMemorySize, GSM_BYTES);
    cudaFuncSetAttribute(flash_h, cudaFuncAttributeMaxDynamicSharedMemorySize, FL_BYTES);

    // one side stream + fork/join events (created once; per-call work is identical)
    static cudaStream_t s1 = nullptr;
    static cudaEvent_t eva = nullptr, evb = nullptr, evc = nullptr, evd = nullptr;
    static int sinit = 0;
    if (sinit == 0) {
        if (cudaStreamCreateWithFlags(&s1, cudaStreamNonBlocking) == cudaSuccess &&
            cudaEventCreateWithFlags(&eva, cudaEventDisableTiming) == cudaSuccess &&
            cudaEventCreateWithFlags(&evb, cudaEventDisableTiming) == cudaSuccess &&
            cudaEventCreateWithFlags(&evc, cudaEventDisableTiming) == cudaSuccess &&
            cudaEventCreateWithFlags(&evd, cudaEventDisableTiming) == cudaSuccess)
            sinit = 1;
        else
            sinit = -1;
    }
    const bool useStreams = (sinit == 1);

    if (useStreams) {
        cudaEventRecord(eva, 0);
        cudaStreamWaitEvent(s1, eva, 0);
        wcvt_all_k<<<3072, 256, 0, s1>>>(Wq, wq_h, Wkv, wkv_h, Wo, wo_h, W1, w1_h, W2, w2_h);
        cudaEventRecord(evb, s1);
    } else {
        wcvt_all_k<<<3072, 256>>>(Wq, wq_h, Wkv, wkv_h, Wo, wo_h, W1, w1_h, W2, w2_h);
    }

    // mod (all 4 batches, one adaW pass) + en detect
    mod2_k<<<97, 256>>>(t_cond, adaW, adab, mod, (const int*)en);
    // both pre-attention LNs in one launch
    ln_pair_k<<<8192, 256>>>(q_x, kv_x, qn_w, kvn_w, mod, qn_h, kvn_h);

    if (useStreams) {
        cudaStreamWaitEvent(0, evb, 0);   // weights ready
        cudaEventRecord(evc, 0);
        cudaStreamWaitEvent(s1, evc, 0);
        gemm_h<0><<<dim3(8, 32), 256, GSM_BYTES, s1>>>(
            qn_h, wq_h, q_h, DD, DD, DD, DD, nullptr, nullptr, 0, nullptr, nullptr);
        cudaEventRecord(evd, s1);
        gemm_h<0><<<dim3(16, 32), 256, GSM_BYTES>>>(
            kvn_h, wkv_h, kv_h, DD, DD, 2 * DD, 2 * DD, nullptr, nullptr, 0, nullptr, nullptr);
        cudaStreamWaitEvent(0, evd, 0);   // q ready
    } else {
        gemm_h<0><<<dim3(8, 32), 256, GSM_BYTES>>>(
            qn_h, wq_h, q_h, DD, DD, DD, DD, nullptr, nullptr, 0, nullptr, nullptr);
        gemm_h<0><<<dim3(16, 32), 256, GSM_BYTES>>>(
            kvn_h, wkv_h, kv_h, DD, DD, 2 * DD, 2 * DD, nullptr, nullptr, 0, nullptr, nullptr);
    }

    // fused attention (RoPE + scores + mask + softmax + PV)
    flash_h<<<dim3(SS / 128, BB * HH), 256, FL_BYTES>>>(
        q_h, kv_h, grp, attn_h, cos_q, sin_q, cos_k, sin_k);

    gemm_h<2><<<dim3(8, 32), 256, GSM_BYTES>>>(
        attn_h, wo_h, x, DD, DD, DD, DD, nullptr, mod, 2 * DD, en, q_x);

    ln_one_k<<<NBS, 256>>>(x, n2_w, mod, 3 * DD, 4 * DD, hh);

    gemm_h<1><<<dim3(32, 32), 256, GSM_BYTES>>>(
        hh, w1_h, h1_h, DD, DD, MRD, MRD, b1, nullptr, 0, nullptr, nullptr);
    gemm_h<2><<<dim3(8, 32), 256, GSM_BYTES>>>(
        h1_h, w2_h, out, MRD, MRD, DD, DD, b2, mod, 5 * DD, en, x);
}